// round 6
// baseline (speedup 1.0000x reference)
#include <cuda_runtime.h>
#include <cuda_bf16.h>
#include <cstdint>

#define N_NODES 8192
#define IN_F    128
#define HID     64
#define OUT_F   128
#define BM      64
#define BN      64
#define NITER   64          // per CTA after j-split (4096 / BN)

// K/V row stride in smem: 64 data bf16 + 8 pad = 72 bf16 = 144 B = 9 uint4.
// ldmatrix phase check: 8 rows spaced 144B -> bank chunks {4i..4i+3}, i=0..7
//  -> all 32 banks distinct -> conflict-free.
#define ROWB  144
#define KSTR4 9
// byte offsets within one buffer: Kh 0, Kl 9216, Vh 18432, Vl 36864
#define OFF_KL 9216
#define OFF_VH 18432
#define OFF_VL 36864
#define BUF_BYTES 55296            // 64*144*2 + 128*144*2
#define BUF_U4 (BUF_BYTES/16)

// ---------------- scratch (static device globals; no allocs allowed) -----
__device__ __align__(16) __nv_bfloat16 g_Qh[N_NODES * HID];
__device__ __align__(16) __nv_bfloat16 g_Ql[N_NODES * HID];
__device__ __align__(16) __nv_bfloat16 g_Kh[N_NODES * HID];
__device__ __align__(16) __nv_bfloat16 g_Kl[N_NODES * HID];
// V stored TRANSPOSED: [OUT_F][N_NODES] so flash-kernel smem fills are coalesced
__device__ __align__(16) __nv_bfloat16 g_Vth[OUT_F * N_NODES];
__device__ __align__(16) __nv_bfloat16 g_Vtl[OUT_F * N_NODES];
// split-j partials
__device__ __align__(16) float g_Op[2][N_NODES][OUT_F];
__device__ float g_pm[2][N_NODES];
__device__ float g_pl[2][N_NODES];

// ---------------- helpers --------------------------------------------------
__device__ __forceinline__ uint32_t smem_u32(const void* p) {
    uint32_t a;
    asm("{ .reg .u64 t; cvta.to.shared.u64 t, %1; cvt.u32.u64 %0, t; }"
        : "=r"(a) : "l"(p));
    return a;
}
__device__ __forceinline__ void cp16(void* s, const void* g) {
    uint32_t sa = smem_u32(s);
    asm volatile("cp.async.cg.shared.global [%0], [%1], 16;\n" :: "r"(sa), "l"(g));
}
__device__ __forceinline__ void cp_commit() { asm volatile("cp.async.commit_group;\n"); }
template <int N> __device__ __forceinline__ void cp_wait() {
    asm volatile("cp.async.wait_group %0;\n" :: "n"(N));
}
__device__ __forceinline__ void ldsm_x4(uint32_t& r0, uint32_t& r1,
                                        uint32_t& r2, uint32_t& r3, uint32_t addr) {
    asm volatile("ldmatrix.sync.aligned.m8n8.x4.shared.b16 {%0,%1,%2,%3}, [%4];"
                 : "=r"(r0), "=r"(r1), "=r"(r2), "=r"(r3) : "r"(addr));
}
__device__ __forceinline__ void mma_bf16(float c[4],
                                         unsigned a0, unsigned a1, unsigned a2, unsigned a3,
                                         unsigned b0, unsigned b1) {
    asm volatile(
        "mma.sync.aligned.m16n8k16.row.col.f32.bf16.bf16.f32 "
        "{%0,%1,%2,%3}, {%4,%5,%6,%7}, {%8,%9}, {%0,%1,%2,%3};\n"
        : "+f"(c[0]), "+f"(c[1]), "+f"(c[2]), "+f"(c[3])
        : "r"(a0), "r"(a1), "r"(a2), "r"(a3), "r"(b0), "r"(b1));
}
__device__ __forceinline__ unsigned pack_bf2(__nv_bfloat16 a, __nv_bfloat16 b) {
    return (unsigned)__bfloat16_as_ushort(a) |
           ((unsigned)__bfloat16_as_ushort(b) << 16);
}

// ---------------- prep: h@[Ws|Wt|Wc] + hi/lo splits ------------------------
// grid 256 x 512 threads; block = 32 rows of h; thread = 2 cols of the
// 256-col concat [Ws|Wt|Wc]; 4 row-groups share identical W addresses (L1).
__global__ __launch_bounds__(512)
void prep_kernel(const float* __restrict__ h,
                 const float* __restrict__ Ws,
                 const float* __restrict__ Wt,
                 const float* __restrict__ Wc) {
    __shared__ float hs[32][128];
    const int rowB = blockIdx.x * 32;
    const int tid  = threadIdx.x;

    const float4* h4 = (const float4*)(h + (size_t)rowB * IN_F);
#pragma unroll
    for (int i = tid; i < 1024; i += 512)
        ((float4*)hs)[i] = h4[i];
    __syncthreads();

    const int rg = tid >> 7;          // row group 0..3 (8 rows each)
    const int ct = tid & 127;
    const int g  = 2 * ct;            // concat col
    const int row0 = rowB + rg * 8;

    const float* W;
    int stride, c;
    if (g < 64)       { W = Ws; stride = 64;  c = g; }
    else if (g < 128) { W = Wt; stride = 64;  c = g - 64; }
    else              { W = Wc; stride = 128; c = g - 128; }

    float acc[8][2];
#pragma unroll
    for (int r = 0; r < 8; r++) { acc[r][0] = 0.f; acc[r][1] = 0.f; }

#pragma unroll 8
    for (int k4 = 0; k4 < 32; k4++) {
        float2 w0 = *(const float2*)&W[(4 * k4 + 0) * stride + c];
        float2 w1 = *(const float2*)&W[(4 * k4 + 1) * stride + c];
        float2 w2 = *(const float2*)&W[(4 * k4 + 2) * stride + c];
        float2 w3 = *(const float2*)&W[(4 * k4 + 3) * stride + c];
#pragma unroll
        for (int r = 0; r < 8; r++) {
            float4 hv = *(const float4*)&hs[rg * 8 + r][4 * k4];
            acc[r][0] += hv.x * w0.x + hv.y * w1.x + hv.z * w2.x + hv.w * w3.x;
            acc[r][1] += hv.x * w0.y + hv.y * w1.y + hv.z * w2.y + hv.w * w3.y;
        }
    }

    if (g < 128) {
        __nv_bfloat16* dh = (g < 64) ? g_Qh : g_Kh;
        __nv_bfloat16* dl = (g < 64) ? g_Ql : g_Kl;
#pragma unroll
        for (int r = 0; r < 8; r++) {
            __nv_bfloat16 h0 = __float2bfloat16(acc[r][0]);
            __nv_bfloat16 h1 = __float2bfloat16(acc[r][1]);
            __nv_bfloat16 e0 = __float2bfloat16(acc[r][0] - __bfloat162float(h0));
            __nv_bfloat16 e1 = __float2bfloat16(acc[r][1] - __bfloat162float(h1));
            *(unsigned*)&dh[(size_t)(row0 + r) * HID + c] = pack_bf2(h0, h1);
            *(unsigned*)&dl[(size_t)(row0 + r) * HID + c] = pack_bf2(e0, e1);
        }
    } else {
#pragma unroll
        for (int j = 0; j < 2; j++) {
            union { __nv_bfloat16 b[8]; uint4 u; } ph, pl;
#pragma unroll
            for (int r = 0; r < 8; r++) {
                float v = acc[r][j];
                __nv_bfloat16 hi = __float2bfloat16(v);
                ph.b[r] = hi;
                pl.b[r] = __float2bfloat16(v - __bfloat162float(hi));
            }
            size_t base = (size_t)(c + j) * N_NODES + row0;  // 8 rows = 16B
            *(uint4*)(g_Vth + base) = ph.u;
            *(uint4*)(g_Vtl + base) = pl.u;
        }
    }
}

// ---------------- flash attention (warp MMA + ldmatrix) --------------------
// grid = 256 CTAs: m-tile = bx & 127, j-half = bx >> 7. 128 threads.
__global__ __launch_bounds__(128, 2)
void flash_kernel(const int* __restrict__ adj) {
    extern __shared__ __align__(16) unsigned char dynsmem[];
    uint4* base4 = (uint4*)dynsmem;
    const uint32_t smem_u = smem_u32(dynsmem);

    const int tid  = threadIdx.x;
    const int warp = tid >> 5;
    const int lane = tid & 31;
    const int lr   = lane >> 2;   // group id (row within 8)
    const int qi   = lane & 3;    // thread-in-group

    const int mtile = blockIdx.x & 127;
    const int jhalf = blockIdx.x >> 7;
    const int jbase = jhalf * (N_NODES / 2);

    const int mr   = mtile * BM + warp * 16;
    const int row0 = mr + lr;
    const int row1 = row0 + 8;

    // per-thread ldmatrix row offset: (lane&7) rows of 144B + (lane>>3)*16B
    const uint32_t lds_off = (uint32_t)((lane & 7) * ROWB + (lane >> 3) * 16);

    // ---- Q fragments (hi/lo), 4 k-tiles of 16 -----------------------
    const unsigned* qh32 = (const unsigned*)g_Qh;
    const unsigned* ql32 = (const unsigned*)g_Ql;
    unsigned qh[4][4], ql[4][4];
#pragma unroll
    for (int kt = 0; kt < 4; kt++) {
        int b0 = row0 * 32 + qi + 8 * kt;
        int b1 = row1 * 32 + qi + 8 * kt;
        qh[kt][0] = qh32[b0];     qh[kt][1] = qh32[b1];
        qh[kt][2] = qh32[b0 + 4]; qh[kt][3] = qh32[b1 + 4];
        ql[kt][0] = ql32[b0];     ql[kt][1] = ql32[b1];
        ql[kt][2] = ql32[b0 + 4]; ql[kt][3] = ql32[b1 + 4];
    }

    float O[16][4];
#pragma unroll
    for (int v = 0; v < 16; v++)
#pragma unroll
        for (int i = 0; i < 4; i++) O[v][i] = 0.f;
    float m0 = -1e30f, m1 = -1e30f, l0 = 0.f, l1 = 0.f;

    const int2*  adj2 = (const int2*)adj;
    const uint4* gKh4 = (const uint4*)g_Kh;
    const uint4* gKl4 = (const uint4*)g_Kl;
    const uint4* gVh4 = (const uint4*)g_Vth;
    const uint4* gVl4 = (const uint4*)g_Vtl;

    // ---- prologue: fill buffer 0 ------------------------------------
    {
        uint4* bKh = base4;
        uint4* bKl = base4 + OFF_KL / 16;
        uint4* bVh = base4 + OFF_VH / 16;
        uint4* bVl = base4 + OFF_VL / 16;
#pragma unroll
        for (int i = tid; i < 512; i += 128) {
            int r = i >> 3, cw = i & 7;
            cp16(&bKh[r * KSTR4 + cw], &gKh4[(jbase + r) * 8 + cw]);
            cp16(&bKl[r * KSTR4 + cw], &gKl4[(jbase + r) * 8 + cw]);
        }
#pragma unroll
        for (int i = tid; i < 1024; i += 128) {
            int cl = i >> 3, kw = i & 7;
            cp16(&bVh[cl * KSTR4 + kw], &gVh4[cl * 1024 + (jbase >> 3) + kw]);
            cp16(&bVl[cl * KSTR4 + kw], &gVl4[cl * 1024 + (jbase >> 3) + kw]);
        }
        cp_commit();
    }

    int buf = 0;
    for (int it = 0; it < NITER; ++it) {
        const int j0 = jbase + it * BN;

        // ---- adj prefetch (each quad covers one full 32B sector) ----
        int2 adjA[8], adjB[8];
#pragma unroll
        for (int nt = 0; nt < 8; nt++) {
            adjA[nt] = __ldcs(&adj2[row0 * 4096 + (j0 >> 1) + 4 * nt + qi]);
            adjB[nt] = __ldcs(&adj2[row1 * 4096 + (j0 >> 1) + 4 * nt + qi]);
        }

        // ---- issue fill of next buffer ------------------------------
        if (it + 1 < NITER) {
            const int jn = j0 + BN;
            uint4* bKh = base4 + (buf ^ 1) * BUF_U4;
            uint4* bKl = bKh + OFF_KL / 16;
            uint4* bVh = bKh + OFF_VH / 16;
            uint4* bVl = bKh + OFF_VL / 16;
#pragma unroll
            for (int i = tid; i < 512; i += 128) {
                int r = i >> 3, cw = i & 7;
                cp16(&bKh[r * KSTR4 + cw], &gKh4[(jn + r) * 8 + cw]);
                cp16(&bKl[r * KSTR4 + cw], &gKl4[(jn + r) * 8 + cw]);
            }
#pragma unroll
            for (int i = tid; i < 1024; i += 128) {
                int cl = i >> 3, kw = i & 7;
                cp16(&bVh[cl * KSTR4 + kw], &gVh4[cl * 1024 + (jn >> 3) + kw]);
                cp16(&bVl[cl * KSTR4 + kw], &gVl4[cl * 1024 + (jn >> 3) + kw]);
            }
            cp_commit();
            cp_wait<1>();   // current buffer's group is done
        } else {
            cp_wait<0>();
        }
        __syncthreads();

        const uint32_t kh_u = smem_u + buf * BUF_BYTES + lds_off;
        const uint32_t kl_u = kh_u + OFF_KL;
        const uint32_t vh_u = kh_u + OFF_VH;
        const uint32_t vl_u = kh_u + OFF_VL;

        // ---- S = Q K^T (3-term bf16 split -> ~fp32 accuracy) --------
        float S[8][4];
#pragma unroll
        for (int nt = 0; nt < 8; nt++) {
            S[nt][0] = S[nt][1] = S[nt][2] = S[nt][3] = 0.f;
            uint32_t bh[8], bl[8];
            ldsm_x4(bh[0], bh[1], bh[2], bh[3], kh_u + nt * 1152);
            ldsm_x4(bh[4], bh[5], bh[6], bh[7], kh_u + nt * 1152 + 64);
            ldsm_x4(bl[0], bl[1], bl[2], bl[3], kl_u + nt * 1152);
            ldsm_x4(bl[4], bl[5], bl[6], bl[7], kl_u + nt * 1152 + 64);
#pragma unroll
            for (int kt = 0; kt < 4; kt++) {
                unsigned bh0 = bh[2 * kt], bh1 = bh[2 * kt + 1];
                unsigned bl0 = bl[2 * kt], bl1 = bl[2 * kt + 1];
                mma_bf16(S[nt], qh[kt][0], qh[kt][1], qh[kt][2], qh[kt][3], bh0, bh1);
                mma_bf16(S[nt], ql[kt][0], ql[kt][1], ql[kt][2], ql[kt][3], bh0, bh1);
                mma_bf16(S[nt], qh[kt][0], qh[kt][1], qh[kt][2], qh[kt][3], bl0, bl1);
            }
        }

        // ---- mask + row max -----------------------------------------
        float rmax0 = -1e30f, rmax1 = -1e30f;
#pragma unroll
        for (int nt = 0; nt < 8; nt++) {
            if (adjA[nt].x <= 0) S[nt][0] = -1e30f;
            if (adjA[nt].y <= 0) S[nt][1] = -1e30f;
            if (adjB[nt].x <= 0) S[nt][2] = -1e30f;
            if (adjB[nt].y <= 0) S[nt][3] = -1e30f;
            rmax0 = fmaxf(rmax0, fmaxf(S[nt][0], S[nt][1]));
            rmax1 = fmaxf(rmax1, fmaxf(S[nt][2], S[nt][3]));
        }
        rmax0 = fmaxf(rmax0, __shfl_xor_sync(0xffffffffu, rmax0, 1));
        rmax0 = fmaxf(rmax0, __shfl_xor_sync(0xffffffffu, rmax0, 2));
        rmax1 = fmaxf(rmax1, __shfl_xor_sync(0xffffffffu, rmax1, 1));
        rmax1 = fmaxf(rmax1, __shfl_xor_sync(0xffffffffu, rmax1, 2));

        float mn0 = fmaxf(m0, rmax0), mn1 = fmaxf(m1, rmax1);
        float sc0 = __expf(m0 - mn0), sc1 = __expf(m1 - mn1);
        m0 = mn0; m1 = mn1;

        // ---- exp + pack P into bf16 hi/lo A-fragments ---------------
        float rs0 = 0.f, rs1 = 0.f;
        unsigned aph[4][4], apl[4][4];
#pragma unroll
        for (int kt2 = 0; kt2 < 4; kt2++) {
#pragma unroll
            for (int half = 0; half < 2; half++) {
                int nt = 2 * kt2 + half;
                float p0 = (S[nt][0] > -1e29f) ? __expf(S[nt][0] - mn0) : 0.f;
                float p1 = (S[nt][1] > -1e29f) ? __expf(S[nt][1] - mn0) : 0.f;
                float p2 = (S[nt][2] > -1e29f) ? __expf(S[nt][2] - mn1) : 0.f;
                float p3 = (S[nt][3] > -1e29f) ? __expf(S[nt][3] - mn1) : 0.f;
                rs0 += p0 + p1;
                rs1 += p2 + p3;
                __nv_bfloat16 h0 = __float2bfloat16(p0), h1 = __float2bfloat16(p1);
                __nv_bfloat16 h2 = __float2bfloat16(p2), h3 = __float2bfloat16(p3);
                __nv_bfloat16 e0 = __float2bfloat16(p0 - __bfloat162float(h0));
                __nv_bfloat16 e1 = __float2bfloat16(p1 - __bfloat162float(h1));
                __nv_bfloat16 e2 = __float2bfloat16(p2 - __bfloat162float(h2));
                __nv_bfloat16 e3 = __float2bfloat16(p3 - __bfloat162float(h3));
                aph[kt2][2 * half + 0] = pack_bf2(h0, h1);  // row g
                aph[kt2][2 * half + 1] = pack_bf2(h2, h3);  // row g+8
                apl[kt2][2 * half + 0] = pack_bf2(e0, e1);
                apl[kt2][2 * half + 1] = pack_bf2(e2, e3);
            }
        }

        rs0 += __shfl_xor_sync(0xffffffffu, rs0, 1);
        rs0 += __shfl_xor_sync(0xffffffffu, rs0, 2);
        rs1 += __shfl_xor_sync(0xffffffffu, rs1, 1);
        rs1 += __shfl_xor_sync(0xffffffffu, rs1, 2);
        l0 = l0 * sc0 + rs0;
        l1 = l1 * sc1 + rs1;

        // ---- rescale O ----------------------------------------------
#pragma unroll
        for (int v = 0; v < 16; v++) {
            O[v][0] *= sc0; O[v][1] *= sc0;
            O[v][2] *= sc1; O[v][3] *= sc1;
        }

        // ---- O += P V (3-term split) --------------------------------
#pragma unroll
        for (int vn = 0; vn < 16; vn++) {
            uint32_t vh[8], vl[8];
            ldsm_x4(vh[0], vh[1], vh[2], vh[3], vh_u + vn * 1152);
            ldsm_x4(vh[4], vh[5], vh[6], vh[7], vh_u + vn * 1152 + 64);
            ldsm_x4(vl[0], vl[1], vl[2], vl[3], vl_u + vn * 1152);
            ldsm_x4(vl[4], vl[5], vl[6], vl[7], vl_u + vn * 1152 + 64);
#pragma unroll
            for (int kt2 = 0; kt2 < 4; kt2++) {
                unsigned vh0 = vh[2 * kt2], vh1 = vh[2 * kt2 + 1];
                unsigned vl0 = vl[2 * kt2], vl1 = vl[2 * kt2 + 1];
                mma_bf16(O[vn], aph[kt2][0], aph[kt2][1], aph[kt2][2], aph[kt2][3], vh0, vh1);
                mma_bf16(O[vn], apl[kt2][0], apl[kt2][1], apl[kt2][2], apl[kt2][3], vh0, vh1);
                mma_bf16(O[vn], aph[kt2][0], aph[kt2][1], aph[kt2][2], aph[kt2][3], vl0, vl1);
            }
        }
        __syncthreads();  // all warps done reading before this buffer is refilled
        buf ^= 1;
    }

    // ---- store partials (unnormalized) ------------------------------
    float* op = &g_Op[jhalf][0][0];
#pragma unroll
    for (int vn = 0; vn < 16; vn++) {
        int col = 8 * vn + 2 * qi;
        *(float2*)&op[row0 * OUT_F + col] = make_float2(O[vn][0], O[vn][1]);
        *(float2*)&op[row1 * OUT_F + col] = make_float2(O[vn][2], O[vn][3]);
    }
    if (qi == 0) {
        g_pm[jhalf][row0] = m0; g_pl[jhalf][row0] = l0;
        g_pm[jhalf][row1] = m1; g_pl[jhalf][row1] = l1;
    }
}

// ---------------- merge the two j-halves ----------------------------------
// grid 1024 x 256: block = 8 rows, thread = 4 cols
__global__ __launch_bounds__(256)
void merge_kernel(float* __restrict__ out) {
    const int row = blockIdx.x * 8 + (threadIdx.x >> 5);
    const int c   = (threadIdx.x & 31) * 4;

    float ma = g_pm[0][row], mb = g_pm[1][row];
    float la = g_pl[0][row], lb = g_pl[1][row];
    float M  = fmaxf(ma, mb);
    float sa = __expf(ma - M), sb = __expf(mb - M);
    float inv = 1.f / (la * sa + lb * sb);

    float4 a = *(const float4*)&g_Op[0][row][c];
    float4 b = *(const float4*)&g_Op[1][row][c];
    float4 r;
    r.x = (a.x * sa + b.x * sb) * inv;
    r.y = (a.y * sa + b.y * sb) * inv;
    r.z = (a.z * sa + b.z * sb) * inv;
    r.w = (a.w * sa + b.w * sb) * inv;
    *(float4*)&out[row * OUT_F + c] = r;
}

// ---------------- launch --------------------------------------------------
extern "C" void kernel_launch(void* const* d_in, const int* in_sizes, int n_in,
                              void* d_out, int out_size) {
    const float* h   = (const float*)d_in[0];
    const int*   adj = (const int*)d_in[1];
    const float* Ws  = (const float*)d_in[2];
    const float* Wt  = (const float*)d_in[3];
    const float* Wc  = (const float*)d_in[4];
    float* out = (float*)d_out;

    prep_kernel<<<N_NODES / 32, 512>>>(h, Ws, Wt, Wc);

    const int smem_bytes = 2 * BUF_BYTES;   // 110592 B
    cudaFuncSetAttribute(flash_kernel,
                         cudaFuncAttributeMaxDynamicSharedMemorySize, smem_bytes);
    flash_kernel<<<256, 128, smem_bytes>>>(adj);

    merge_kernel<<<N_NODES / 8, 256>>>(out);
}

// round 7
// speedup vs baseline: 1.5929x; 1.5929x over previous
#include <cuda_runtime.h>
#include <cuda_bf16.h>
#include <cstdint>

#define N_NODES 8192
#define IN_F    128
#define HID     64
#define OUT_F   128
#define BM      64
#define BN      64
#define NITER   64          // per CTA after j-split (4096 / BN)

// K/V row stride in smem: 64 data bf16 + 8 pad = 72 bf16 = 36 words = 9 uint4.
// Bank check (LDS.32): word addr = 36*n + j, lanes n=lr(0..7), j=qi(0..3)
//  -> bank = (4n + j) mod 32 : all 32 distinct -> conflict-free.
#define KSTRW 36
#define KSTR4 9
// uint4 sizes per buffer: Kh 576, Kl 576, Vh 1152, Vl 1152 -> 3456 u4 = 55296 B
#define BUF_U4 3456

// ---------------- scratch (static device globals; no allocs allowed) -----
__device__ __align__(16) __nv_bfloat16 g_Qh[N_NODES * HID];
__device__ __align__(16) __nv_bfloat16 g_Ql[N_NODES * HID];
__device__ __align__(16) __nv_bfloat16 g_Kh[N_NODES * HID];
__device__ __align__(16) __nv_bfloat16 g_Kl[N_NODES * HID];
// V stored TRANSPOSED: [OUT_F][N_NODES] so flash-kernel smem fills are coalesced
__device__ __align__(16) __nv_bfloat16 g_Vth[OUT_F * N_NODES];
__device__ __align__(16) __nv_bfloat16 g_Vtl[OUT_F * N_NODES];
// split-j partials
__device__ __align__(16) float g_Op[2][N_NODES][OUT_F];
__device__ float g_pm[2][N_NODES];
__device__ float g_pl[2][N_NODES];

// ---------------- cp.async helpers ---------------------------------------
__device__ __forceinline__ void cp16(void* s, const void* g) {
    unsigned sa = (unsigned)__cvta_generic_to_shared(s);
    asm volatile("cp.async.cg.shared.global [%0], [%1], 16;\n" :: "r"(sa), "l"(g));
}
__device__ __forceinline__ void cp_commit() {
    asm volatile("cp.async.commit_group;\n");
}
template <int N>
__device__ __forceinline__ void cp_wait() {
    asm volatile("cp.async.wait_group %0;\n" :: "n"(N));
}

// ---------------- prep: h@[Ws|Wt|Wc] + hi/lo splits ------------------------
// grid 512 x 128 threads; block = 16 rows of h (two 8-row halves);
// thread handles 4 cols of the 256-col concat [Ws|Wt|Wc], float4 W loads.
__global__ __launch_bounds__(128)
void prep_kernel(const float* __restrict__ h,
                 const float* __restrict__ Ws,
                 const float* __restrict__ Wt,
                 const float* __restrict__ Wc) {
    __shared__ float hs[16][128];
    const int rowB = blockIdx.x * 16;
    const int tid  = threadIdx.x;

    const float4* h4 = (const float4*)(h + (size_t)rowB * IN_F);
#pragma unroll
    for (int i = tid; i < 512; i += 128)
        ((float4*)hs)[i] = h4[i];
    __syncthreads();

    const int half = tid >> 6;          // 0 / 1: rows 0-7 / 8-15
    const int ct   = tid & 63;
    const int g    = 4 * ct;            // concat col
    const int row0 = rowB + half * 8;

    const float* W;
    int stride, c;
    if (g < 64)       { W = Ws; stride = 64;  c = g; }
    else if (g < 128) { W = Wt; stride = 64;  c = g - 64; }
    else              { W = Wc; stride = 128; c = g - 128; }

    float acc[8][4];
#pragma unroll
    for (int r = 0; r < 8; r++)
#pragma unroll
        for (int j = 0; j < 4; j++) acc[r][j] = 0.f;

#pragma unroll 4
    for (int k = 0; k < 128; k++) {
        float4 w = *(const float4*)&W[k * stride + c];   // 16B coalesced
#pragma unroll
        for (int r = 0; r < 8; r++) {
            float hv = hs[half * 8 + r][k];              // broadcast
            acc[r][0] += hv * w.x;
            acc[r][1] += hv * w.y;
            acc[r][2] += hv * w.z;
            acc[r][3] += hv * w.w;
        }
    }

    if (g < 128) {
        __nv_bfloat16* dh = (g < 64) ? g_Qh : g_Kh;
        __nv_bfloat16* dl = (g < 64) ? g_Ql : g_Kl;
#pragma unroll
        for (int r = 0; r < 8; r++) {
            union { __nv_bfloat16 b[4]; uint2 u; } ph, pl;
#pragma unroll
            for (int j = 0; j < 4; j++) {
                float v = acc[r][j];
                __nv_bfloat16 hi = __float2bfloat16(v);
                ph.b[j] = hi;
                pl.b[j] = __float2bfloat16(v - __bfloat162float(hi));
            }
            *(uint2*)&dh[(size_t)(row0 + r) * HID + c] = ph.u;
            *(uint2*)&dl[(size_t)(row0 + r) * HID + c] = pl.u;
        }
    } else {
#pragma unroll
        for (int j = 0; j < 4; j++) {
            union { __nv_bfloat16 b[8]; uint4 u; } ph, pl;
#pragma unroll
            for (int r = 0; r < 8; r++) {
                float v = acc[r][j];
                __nv_bfloat16 hi = __float2bfloat16(v);
                ph.b[r] = hi;
                pl.b[r] = __float2bfloat16(v - __bfloat162float(hi));
            }
            size_t base = (size_t)(c + j) * N_NODES + row0;  // 8 rows = 16B
            *(uint4*)(g_Vth + base) = ph.u;
            *(uint4*)(g_Vtl + base) = pl.u;
        }
    }
}

// ---------------- flash attention ----------------------------------------
__device__ __forceinline__ void mma_bf16(float c[4],
                                         unsigned a0, unsigned a1, unsigned a2, unsigned a3,
                                         unsigned b0, unsigned b1) {
    asm volatile(
        "mma.sync.aligned.m16n8k16.row.col.f32.bf16.bf16.f32 "
        "{%0,%1,%2,%3}, {%4,%5,%6,%7}, {%8,%9}, {%0,%1,%2,%3};\n"
        : "+f"(c[0]), "+f"(c[1]), "+f"(c[2]), "+f"(c[3])
        : "r"(a0), "r"(a1), "r"(a2), "r"(a3), "r"(b0), "r"(b1));
}

__device__ __forceinline__ unsigned pack_bf2(__nv_bfloat16 a, __nv_bfloat16 b) {
    return (unsigned)__bfloat16_as_ushort(a) |
           ((unsigned)__bfloat16_as_ushort(b) << 16);
}

// grid = 256 CTAs: m-tile = bx & 127, j-half = bx >> 7. 128 threads.
__global__ __launch_bounds__(128, 2)
void flash_kernel(const int* __restrict__ adj) {
    extern __shared__ __align__(16) unsigned char dynsmem[];
    uint4* base4 = (uint4*)dynsmem;

    const int tid  = threadIdx.x;
    const int warp = tid >> 5;
    const int lane = tid & 31;
    const int lr   = lane >> 2;   // group id (row within 8)
    const int qi   = lane & 3;    // thread-in-group

    const int mtile = blockIdx.x & 127;
    const int jhalf = blockIdx.x >> 7;
    const int jbase = jhalf * (N_NODES / 2);

    const int mr   = mtile * BM + warp * 16;
    const int row0 = mr + lr;
    const int row1 = row0 + 8;

    // ---- Q fragments (hi/lo), 4 k-tiles of 16 -----------------------
    const unsigned* qh32 = (const unsigned*)g_Qh;
    const unsigned* ql32 = (const unsigned*)g_Ql;
    unsigned qh[4][4], ql[4][4];
#pragma unroll
    for (int kt = 0; kt < 4; kt++) {
        int b0 = row0 * 32 + qi + 8 * kt;
        int b1 = row1 * 32 + qi + 8 * kt;
        qh[kt][0] = qh32[b0];     qh[kt][1] = qh32[b1];
        qh[kt][2] = qh32[b0 + 4]; qh[kt][3] = qh32[b1 + 4];
        ql[kt][0] = ql32[b0];     ql[kt][1] = ql32[b1];
        ql[kt][2] = ql32[b0 + 4]; ql[kt][3] = ql32[b1 + 4];
    }

    float O[16][4];
#pragma unroll
    for (int v = 0; v < 16; v++)
#pragma unroll
        for (int i = 0; i < 4; i++) O[v][i] = 0.f;
    float m0 = -1e30f, m1 = -1e30f, l0 = 0.f, l1 = 0.f;

    const int2*  adj2 = (const int2*)adj;
    const uint4* gKh4 = (const uint4*)g_Kh;
    const uint4* gKl4 = (const uint4*)g_Kl;
    const uint4* gVh4 = (const uint4*)g_Vth;
    const uint4* gVl4 = (const uint4*)g_Vtl;

    // ---- prologue: fill buffer 0 ------------------------------------
    {
        uint4* bKh = base4;
        uint4* bKl = base4 + 576;
        uint4* bVh = base4 + 1152;
        uint4* bVl = base4 + 2304;
#pragma unroll
        for (int i = tid; i < 512; i += 128) {
            int r = i >> 3, cw = i & 7;
            cp16(&bKh[r * KSTR4 + cw], &gKh4[(jbase + r) * 8 + cw]);
            cp16(&bKl[r * KSTR4 + cw], &gKl4[(jbase + r) * 8 + cw]);
        }
#pragma unroll
        for (int i = tid; i < 1024; i += 128) {
            int cl = i >> 3, kw = i & 7;
            cp16(&bVh[cl * KSTR4 + kw], &gVh4[cl * 1024 + (jbase >> 3) + kw]);
            cp16(&bVl[cl * KSTR4 + kw], &gVl4[cl * 1024 + (jbase >> 3) + kw]);
        }
        cp_commit();
    }

    int buf = 0;
    for (int it = 0; it < NITER; ++it) {
        const int j0 = jbase + it * BN;

        // ---- adj prefetch (each quad covers one full 32B sector) ----
        int2 adjA[8], adjB[8];
#pragma unroll
        for (int nt = 0; nt < 8; nt++) {
            adjA[nt] = __ldcs(&adj2[row0 * 4096 + (j0 >> 1) + 4 * nt + qi]);
            adjB[nt] = __ldcs(&adj2[row1 * 4096 + (j0 >> 1) + 4 * nt + qi]);
        }

        // ---- issue fill of next buffer ------------------------------
        if (it + 1 < NITER) {
            const int jn = j0 + BN;
            uint4* bKh = base4 + (buf ^ 1) * BUF_U4;
            uint4* bKl = bKh + 576;
            uint4* bVh = bKh + 1152;
            uint4* bVl = bKh + 2304;
#pragma unroll
            for (int i = tid; i < 512; i += 128) {
                int r = i >> 3, cw = i & 7;
                cp16(&bKh[r * KSTR4 + cw], &gKh4[(jn + r) * 8 + cw]);
                cp16(&bKl[r * KSTR4 + cw], &gKl4[(jn + r) * 8 + cw]);
            }
#pragma unroll
            for (int i = tid; i < 1024; i += 128) {
                int cl = i >> 3, kw = i & 7;
                cp16(&bVh[cl * KSTR4 + kw], &gVh4[cl * 1024 + (jn >> 3) + kw]);
                cp16(&bVl[cl * KSTR4 + kw], &gVl4[cl * 1024 + (jn >> 3) + kw]);
            }
            cp_commit();
            cp_wait<1>();   // current buffer's group is done
        } else {
            cp_wait<0>();
        }
        __syncthreads();

        const unsigned* sKh32 = (const unsigned*)(base4 + buf * BUF_U4);
        const unsigned* sKl32 = sKh32 + 576 * 4;
        const unsigned* sVh32 = sKh32 + 1152 * 4;
        const unsigned* sVl32 = sKh32 + 2304 * 4;

        // ---- S = Q K^T (3-term bf16 split, chains interleaved x4) ---
        float S[8][4];
#pragma unroll
        for (int nt = 0; nt < 8; nt++)
            S[nt][0] = S[nt][1] = S[nt][2] = S[nt][3] = 0.f;

#pragma unroll
        for (int kt = 0; kt < 4; kt++) {
#pragma unroll
            for (int gr = 0; gr < 2; gr++) {          // nt groups of 4
                unsigned b0[4], b1[4], c0[4], c1[4];
#pragma unroll
                for (int i = 0; i < 4; i++) {
                    int nt = 4 * gr + i;
                    int bi = (8 * nt + lr) * KSTRW + qi + 8 * kt;
                    b0[i] = sKh32[bi]; b1[i] = sKh32[bi + 4];
                    c0[i] = sKl32[bi]; c1[i] = sKl32[bi + 4];
                }
#pragma unroll
                for (int i = 0; i < 4; i++)
                    mma_bf16(S[4*gr+i], qh[kt][0], qh[kt][1], qh[kt][2], qh[kt][3], b0[i], b1[i]);
#pragma unroll
                for (int i = 0; i < 4; i++)
                    mma_bf16(S[4*gr+i], ql[kt][0], ql[kt][1], ql[kt][2], ql[kt][3], b0[i], b1[i]);
#pragma unroll
                for (int i = 0; i < 4; i++)
                    mma_bf16(S[4*gr+i], qh[kt][0], qh[kt][1], qh[kt][2], qh[kt][3], c0[i], c1[i]);
            }
        }

        // ---- mask + row max -----------------------------------------
        float rmax0 = -1e30f, rmax1 = -1e30f;
#pragma unroll
        for (int nt = 0; nt < 8; nt++) {
            if (adjA[nt].x <= 0) S[nt][0] = -1e30f;
            if (adjA[nt].y <= 0) S[nt][1] = -1e30f;
            if (adjB[nt].x <= 0) S[nt][2] = -1e30f;
            if (adjB[nt].y <= 0) S[nt][3] = -1e30f;
            rmax0 = fmaxf(rmax0, fmaxf(S[nt][0], S[nt][1]));
            rmax1 = fmaxf(rmax1, fmaxf(S[nt][2], S[nt][3]));
        }
        rmax0 = fmaxf(rmax0, __shfl_xor_sync(0xffffffffu, rmax0, 1));
        rmax0 = fmaxf(rmax0, __shfl_xor_sync(0xffffffffu, rmax0, 2));
        rmax1 = fmaxf(rmax1, __shfl_xor_sync(0xffffffffu, rmax1, 1));
        rmax1 = fmaxf(rmax1, __shfl_xor_sync(0xffffffffu, rmax1, 2));

        float mn0 = fmaxf(m0, rmax0), mn1 = fmaxf(m1, rmax1);
        float sc0 = __expf(m0 - mn0), sc1 = __expf(m1 - mn1);
        m0 = mn0; m1 = mn1;

        // ---- exp + pack P into bf16 hi/lo A-fragments ---------------
        float rs0 = 0.f, rs1 = 0.f;
        unsigned aph[4][4], apl[4][4];
#pragma unroll
        for (int kt2 = 0; kt2 < 4; kt2++) {
#pragma unroll
            for (int half = 0; half < 2; half++) {
                int nt = 2 * kt2 + half;
                float p0 = (S[nt][0] > -1e29f) ? __expf(S[nt][0] - mn0) : 0.f;
                float p1 = (S[nt][1] > -1e29f) ? __expf(S[nt][1] - mn0) : 0.f;
                float p2 = (S[nt][2] > -1e29f) ? __expf(S[nt][2] - mn1) : 0.f;
                float p3 = (S[nt][3] > -1e29f) ? __expf(S[nt][3] - mn1) : 0.f;
                rs0 += p0 + p1;
                rs1 += p2 + p3;
                __nv_bfloat16 h0 = __float2bfloat16(p0), h1 = __float2bfloat16(p1);
                __nv_bfloat16 h2 = __float2bfloat16(p2), h3 = __float2bfloat16(p3);
                __nv_bfloat16 e0 = __float2bfloat16(p0 - __bfloat162float(h0));
                __nv_bfloat16 e1 = __float2bfloat16(p1 - __bfloat162float(h1));
                __nv_bfloat16 e2 = __float2bfloat16(p2 - __bfloat162float(h2));
                __nv_bfloat16 e3 = __float2bfloat16(p3 - __bfloat162float(h3));
                aph[kt2][2 * half + 0] = pack_bf2(h0, h1);  // row g
                aph[kt2][2 * half + 1] = pack_bf2(h2, h3);  // row g+8
                apl[kt2][2 * half + 0] = pack_bf2(e0, e1);
                apl[kt2][2 * half + 1] = pack_bf2(e2, e3);
            }
        }

        rs0 += __shfl_xor_sync(0xffffffffu, rs0, 1);
        rs0 += __shfl_xor_sync(0xffffffffu, rs0, 2);
        rs1 += __shfl_xor_sync(0xffffffffu, rs1, 1);
        rs1 += __shfl_xor_sync(0xffffffffu, rs1, 2);
        l0 = l0 * sc0 + rs0;
        l1 = l1 * sc1 + rs1;

        // ---- rescale O ----------------------------------------------
#pragma unroll
        for (int v = 0; v < 16; v++) {
            O[v][0] *= sc0; O[v][1] *= sc0;
            O[v][2] *= sc1; O[v][3] *= sc1;
        }

        // ---- O += P V (3-term split, chains interleaved x4) ---------
#pragma unroll
        for (int kt2 = 0; kt2 < 4; kt2++) {
#pragma unroll
            for (int gr = 0; gr < 4; gr++) {          // vn groups of 4
                unsigned v0[4], v1[4], w0[4], w1[4];
#pragma unroll
                for (int i = 0; i < 4; i++) {
                    int vn = 4 * gr + i;
                    int bi = (8 * vn + lr) * KSTRW + qi + 8 * kt2;
                    v0[i] = sVh32[bi]; v1[i] = sVh32[bi + 4];
                    w0[i] = sVl32[bi]; w1[i] = sVl32[bi + 4];
                }
#pragma unroll
                for (int i = 0; i < 4; i++)
                    mma_bf16(O[4*gr+i], aph[kt2][0], aph[kt2][1], aph[kt2][2], aph[kt2][3], v0[i], v1[i]);
#pragma unroll
                for (int i = 0; i < 4; i++)
                    mma_bf16(O[4*gr+i], apl[kt2][0], apl[kt2][1], apl[kt2][2], apl[kt2][3], v0[i], v1[i]);
#pragma unroll
                for (int i = 0; i < 4; i++)
                    mma_bf16(O[4*gr+i], aph[kt2][0], aph[kt2][1], aph[kt2][2], aph[kt2][3], w0[i], w1[i]);
            }
        }
        __syncthreads();  // all warps done reading before next refill
        buf ^= 1;
    }

    // ---- store partials (unnormalized) ------------------------------
    float* op = &g_Op[jhalf][0][0];
#pragma unroll
    for (int vn = 0; vn < 16; vn++) {
        int col = 8 * vn + 2 * qi;
        *(float2*)&op[row0 * OUT_F + col] = make_float2(O[vn][0], O[vn][1]);
        *(float2*)&op[row1 * OUT_F + col] = make_float2(O[vn][2], O[vn][3]);
    }
    if (qi == 0) {
        g_pm[jhalf][row0] = m0; g_pl[jhalf][row0] = l0;
        g_pm[jhalf][row1] = m1; g_pl[jhalf][row1] = l1;
    }
}

// ---------------- merge the two j-halves ----------------------------------
// grid 1024 x 256: block = 8 rows, thread = 4 cols
__global__ __launch_bounds__(256)
void merge_kernel(float* __restrict__ out) {
    const int row = blockIdx.x * 8 + (threadIdx.x >> 5);
    const int c   = (threadIdx.x & 31) * 4;

    float ma = g_pm[0][row], mb = g_pm[1][row];
    float la = g_pl[0][row], lb = g_pl[1][row];
    float M  = fmaxf(ma, mb);
    float sa = __expf(ma - M), sb = __expf(mb - M);
    float inv = 1.f / (la * sa + lb * sb);

    float4 a = *(const float4*)&g_Op[0][row][c];
    float4 b = *(const float4*)&g_Op[1][row][c];
    float4 r;
    r.x = (a.x * sa + b.x * sb) * inv;
    r.y = (a.y * sa + b.y * sb) * inv;
    r.z = (a.z * sa + b.z * sb) * inv;
    r.w = (a.w * sa + b.w * sb) * inv;
    *(float4*)&out[row * OUT_F + c] = r;
}

// ---------------- launch --------------------------------------------------
extern "C" void kernel_launch(void* const* d_in, const int* in_sizes, int n_in,
                              void* d_out, int out_size) {
    const float* h   = (const float*)d_in[0];
    const int*   adj = (const int*)d_in[1];
    const float* Ws  = (const float*)d_in[2];
    const float* Wt  = (const float*)d_in[3];
    const float* Wc  = (const float*)d_in[4];
    float* out = (float*)d_out;

    prep_kernel<<<N_NODES / 16, 128>>>(h, Ws, Wt, Wc);

    const int smem_bytes = 2 * BUF_U4 * 16;   // 110592 B
    cudaFuncSetAttribute(flash_kernel,
                         cudaFuncAttributeMaxDynamicSharedMemorySize, smem_bytes);
    flash_kernel<<<256, 128, smem_bytes>>>(adj);

    merge_kernel<<<N_NODES / 8, 256>>>(out);
}

// round 8
// speedup vs baseline: 2.1848x; 1.3716x over previous
#include <cuda_runtime.h>
#include <cuda_bf16.h>
#include <cuda_fp16.h>
#include <cstdint>

#define N_NODES 8192
#define IN_F    128
#define HID     64
#define OUT_F   128
#define BM      64
#define BN      64
#define NITER   64          // per CTA after j-split (4096 / BN)

// K/V row stride in smem: 64 data elems + 8 pad = 72 x 2B = 144 B = 36 words = 9 uint4.
// Bank check (LDS.32): word addr = 36*n + j, lanes n=lr(0..7), j=qi(0..3)
//  -> bank = (4n + j) mod 32 : all 32 distinct -> conflict-free.
#define KSTRW 36
#define KSTR4 9
// uint4 per buffer: Kh 576, Kl 576, Vh 1152 -> 2304 u4 = 36864 B
#define BUF_U4 2304

// ---------------- scratch (static device globals; no allocs allowed) -----
__device__ __align__(16) __nv_bfloat16 g_Qh[N_NODES * HID];
__device__ __align__(16) __nv_bfloat16 g_Ql[N_NODES * HID];
__device__ __align__(16) __nv_bfloat16 g_Kh[N_NODES * HID];
__device__ __align__(16) __nv_bfloat16 g_Kl[N_NODES * HID];
// V stored TRANSPOSED [OUT_F][N_NODES] as fp16 (single precision term for PV)
__device__ __align__(16) __half g_Vt[OUT_F * N_NODES];
// split-j partials
__device__ __align__(16) float g_Op[2][N_NODES][OUT_F];
__device__ float g_pm[2][N_NODES];
__device__ float g_pl[2][N_NODES];

// ---------------- cp.async helpers ---------------------------------------
__device__ __forceinline__ void cp16(void* s, const void* g) {
    unsigned sa = (unsigned)__cvta_generic_to_shared(s);
    asm volatile("cp.async.cg.shared.global [%0], [%1], 16;\n" :: "r"(sa), "l"(g));
}
__device__ __forceinline__ void cp_commit() {
    asm volatile("cp.async.commit_group;\n");
}
template <int N>
__device__ __forceinline__ void cp_wait() {
    asm volatile("cp.async.wait_group %0;\n" :: "n"(N));
}

// ---------------- prep: h@[Ws|Wt|Wc] + splits ------------------------------
// grid 2048 x 128 threads; block = 4 rows of h; thread = 2 rows x 4 cols of
// the 256-col concat [Ws|Wt|Wc]. High block count -> ~14 blocks/SM, latency hidden.
__global__ __launch_bounds__(128)
void prep_kernel(const float* __restrict__ h,
                 const float* __restrict__ Ws,
                 const float* __restrict__ Wt,
                 const float* __restrict__ Wc) {
    __shared__ float hs[4][128];
    const int rowB = blockIdx.x * 4;
    const int tid  = threadIdx.x;

    const float4* h4 = (const float4*)(h + (size_t)rowB * IN_F);
    ((float4*)hs)[tid] = h4[tid];           // 128 float4 = 4 rows
    __syncthreads();

    const int rg   = tid >> 6;              // row group 0/1 (2 rows each)
    const int ct   = tid & 63;
    const int g    = 4 * ct;                // concat col
    const int row0 = rowB + rg * 2;

    const float* W;
    int stride, c;
    if (g < 64)       { W = Ws; stride = 64;  c = g; }
    else if (g < 128) { W = Wt; stride = 64;  c = g - 64; }
    else              { W = Wc; stride = 128; c = g - 128; }

    float acc[2][4];
#pragma unroll
    for (int r = 0; r < 2; r++)
#pragma unroll
        for (int j = 0; j < 4; j++) acc[r][j] = 0.f;

#pragma unroll 8
    for (int k = 0; k < 128; k++) {
        float4 w = *(const float4*)&W[k * stride + c];   // 16B coalesced, L1-hot
        float hv0 = hs[rg * 2 + 0][k];
        float hv1 = hs[rg * 2 + 1][k];
        acc[0][0] += hv0 * w.x; acc[0][1] += hv0 * w.y;
        acc[0][2] += hv0 * w.z; acc[0][3] += hv0 * w.w;
        acc[1][0] += hv1 * w.x; acc[1][1] += hv1 * w.y;
        acc[1][2] += hv1 * w.z; acc[1][3] += hv1 * w.w;
    }

    if (g < 128) {
        __nv_bfloat16* dh = (g < 64) ? g_Qh : g_Kh;
        __nv_bfloat16* dl = (g < 64) ? g_Ql : g_Kl;
#pragma unroll
        for (int r = 0; r < 2; r++) {
            union { __nv_bfloat16 b[4]; uint2 u; } ph, pl;
#pragma unroll
            for (int j = 0; j < 4; j++) {
                float v = acc[r][j];
                __nv_bfloat16 hi = __float2bfloat16(v);
                ph.b[j] = hi;
                pl.b[j] = __float2bfloat16(v - __bfloat162float(hi));
            }
            *(uint2*)&dh[(size_t)(row0 + r) * HID + c] = ph.u;
            *(uint2*)&dl[(size_t)(row0 + r) * HID + c] = pl.u;
        }
    } else {
        // V transposed, fp16: 2 consecutive rows -> one 4B store per col
#pragma unroll
        for (int j = 0; j < 4; j++) {
            __half v0 = __float2half_rn(acc[0][j]);
            __half v1 = __float2half_rn(acc[1][j]);
            unsigned pk = (unsigned)__half_as_ushort(v0) |
                          ((unsigned)__half_as_ushort(v1) << 16);
            *(unsigned*)&g_Vt[(size_t)(c + j) * N_NODES + row0] = pk;
        }
    }
}

// ---------------- flash attention ----------------------------------------
__device__ __forceinline__ void mma_bf16(float c[4],
                                         unsigned a0, unsigned a1, unsigned a2, unsigned a3,
                                         unsigned b0, unsigned b1) {
    asm volatile(
        "mma.sync.aligned.m16n8k16.row.col.f32.bf16.bf16.f32 "
        "{%0,%1,%2,%3}, {%4,%5,%6,%7}, {%8,%9}, {%0,%1,%2,%3};\n"
        : "+f"(c[0]), "+f"(c[1]), "+f"(c[2]), "+f"(c[3])
        : "r"(a0), "r"(a1), "r"(a2), "r"(a3), "r"(b0), "r"(b1));
}
__device__ __forceinline__ void mma_f16(float c[4],
                                        unsigned a0, unsigned a1, unsigned a2, unsigned a3,
                                        unsigned b0, unsigned b1) {
    asm volatile(
        "mma.sync.aligned.m16n8k16.row.col.f32.f16.f16.f32 "
        "{%0,%1,%2,%3}, {%4,%5,%6,%7}, {%8,%9}, {%0,%1,%2,%3};\n"
        : "+f"(c[0]), "+f"(c[1]), "+f"(c[2]), "+f"(c[3])
        : "r"(a0), "r"(a1), "r"(a2), "r"(a3), "r"(b0), "r"(b1));
}
__device__ __forceinline__ unsigned pack_bf2(__nv_bfloat16 a, __nv_bfloat16 b) {
    return (unsigned)__bfloat16_as_ushort(a) |
           ((unsigned)__bfloat16_as_ushort(b) << 16);
}
__device__ __forceinline__ unsigned pack_h2(__half a, __half b) {
    return (unsigned)__half_as_ushort(a) |
           ((unsigned)__half_as_ushort(b) << 16);
}

// grid = 256 CTAs: m-tile = bx & 127, j-half = bx >> 7. 128 threads.
__global__ __launch_bounds__(128, 2)
void flash_kernel(const int* __restrict__ adj) {
    extern __shared__ __align__(16) unsigned char dynsmem[];
    uint4* base4 = (uint4*)dynsmem;

    const int tid  = threadIdx.x;
    const int warp = tid >> 5;
    const int lane = tid & 31;
    const int lr   = lane >> 2;   // group id (row within 8)
    const int qi   = lane & 3;    // thread-in-group

    const int mtile = blockIdx.x & 127;
    const int jhalf = blockIdx.x >> 7;
    const int jbase = jhalf * (N_NODES / 2);

    const int mr   = mtile * BM + warp * 16;
    const int row0 = mr + lr;
    const int row1 = row0 + 8;

    // ---- Q fragments (hi/lo), 4 k-tiles of 16 -----------------------
    const unsigned* qh32 = (const unsigned*)g_Qh;
    const unsigned* ql32 = (const unsigned*)g_Ql;
    unsigned qh[4][4], ql[4][4];
#pragma unroll
    for (int kt = 0; kt < 4; kt++) {
        int b0 = row0 * 32 + qi + 8 * kt;
        int b1 = row1 * 32 + qi + 8 * kt;
        qh[kt][0] = qh32[b0];     qh[kt][1] = qh32[b1];
        qh[kt][2] = qh32[b0 + 4]; qh[kt][3] = qh32[b1 + 4];
        ql[kt][0] = ql32[b0];     ql[kt][1] = ql32[b1];
        ql[kt][2] = ql32[b0 + 4]; ql[kt][3] = ql32[b1 + 4];
    }

    float O[16][4];
#pragma unroll
    for (int v = 0; v < 16; v++)
#pragma unroll
        for (int i = 0; i < 4; i++) O[v][i] = 0.f;
    float m0 = -1e30f, m1 = -1e30f, l0 = 0.f, l1 = 0.f;

    const int2*  adj2 = (const int2*)adj;
    const uint4* gKh4 = (const uint4*)g_Kh;
    const uint4* gKl4 = (const uint4*)g_Kl;
    const uint4* gV4  = (const uint4*)g_Vt;

    // ---- prologue: fill buffer 0 ------------------------------------
    {
        uint4* bKh = base4;
        uint4* bKl = base4 + 576;
        uint4* bVh = base4 + 1152;
#pragma unroll
        for (int i = tid; i < 512; i += 128) {
            int r = i >> 3, cw = i & 7;
            cp16(&bKh[r * KSTR4 + cw], &gKh4[(jbase + r) * 8 + cw]);
            cp16(&bKl[r * KSTR4 + cw], &gKl4[(jbase + r) * 8 + cw]);
        }
#pragma unroll
        for (int i = tid; i < 1024; i += 128) {
            int cl = i >> 3, kw = i & 7;
            cp16(&bVh[cl * KSTR4 + kw], &gV4[cl * 1024 + (jbase >> 3) + kw]);
        }
        cp_commit();
    }

    int buf = 0;
    for (int it = 0; it < NITER; ++it) {
        const int j0 = jbase + it * BN;

        // ---- adj prefetch (each quad covers one full 32B sector) ----
        int2 adjA[8], adjB[8];
#pragma unroll
        for (int nt = 0; nt < 8; nt++) {
            adjA[nt] = __ldcs(&adj2[row0 * 4096 + (j0 >> 1) + 4 * nt + qi]);
            adjB[nt] = __ldcs(&adj2[row1 * 4096 + (j0 >> 1) + 4 * nt + qi]);
        }

        // ---- issue fill of next buffer ------------------------------
        if (it + 1 < NITER) {
            const int jn = j0 + BN;
            uint4* bKh = base4 + (buf ^ 1) * BUF_U4;
            uint4* bKl = bKh + 576;
            uint4* bVh = bKh + 1152;
#pragma unroll
            for (int i = tid; i < 512; i += 128) {
                int r = i >> 3, cw = i & 7;
                cp16(&bKh[r * KSTR4 + cw], &gKh4[(jn + r) * 8 + cw]);
                cp16(&bKl[r * KSTR4 + cw], &gKl4[(jn + r) * 8 + cw]);
            }
#pragma unroll
            for (int i = tid; i < 1024; i += 128) {
                int cl = i >> 3, kw = i & 7;
                cp16(&bVh[cl * KSTR4 + kw], &gV4[cl * 1024 + (jn >> 3) + kw]);
            }
            cp_commit();
            cp_wait<1>();   // current buffer's group is done
        } else {
            cp_wait<0>();
        }
        __syncthreads();

        const unsigned* sKh32 = (const unsigned*)(base4 + buf * BUF_U4);
        const unsigned* sKl32 = sKh32 + 576 * 4;
        const unsigned* sV32  = sKh32 + 1152 * 4;

        // ---- S = Q K^T (3-term bf16 split, chains interleaved x4) ---
        float S[8][4];
#pragma unroll
        for (int nt = 0; nt < 8; nt++)
            S[nt][0] = S[nt][1] = S[nt][2] = S[nt][3] = 0.f;

#pragma unroll
        for (int kt = 0; kt < 4; kt++) {
#pragma unroll
            for (int gr = 0; gr < 2; gr++) {          // nt groups of 4
                unsigned b0[4], b1[4], c0[4], c1[4];
#pragma unroll
                for (int i = 0; i < 4; i++) {
                    int nt = 4 * gr + i;
                    int bi = (8 * nt + lr) * KSTRW + qi + 8 * kt;
                    b0[i] = sKh32[bi]; b1[i] = sKh32[bi + 4];
                    c0[i] = sKl32[bi]; c1[i] = sKl32[bi + 4];
                }
#pragma unroll
                for (int i = 0; i < 4; i++)
                    mma_bf16(S[4*gr+i], qh[kt][0], qh[kt][1], qh[kt][2], qh[kt][3], b0[i], b1[i]);
#pragma unroll
                for (int i = 0; i < 4; i++)
                    mma_bf16(S[4*gr+i], ql[kt][0], ql[kt][1], ql[kt][2], ql[kt][3], b0[i], b1[i]);
#pragma unroll
                for (int i = 0; i < 4; i++)
                    mma_bf16(S[4*gr+i], qh[kt][0], qh[kt][1], qh[kt][2], qh[kt][3], c0[i], c1[i]);
            }
        }

        // ---- mask + row max -----------------------------------------
        float rmax0 = -1e30f, rmax1 = -1e30f;
#pragma unroll
        for (int nt = 0; nt < 8; nt++) {
            if (adjA[nt].x <= 0) S[nt][0] = -1e30f;
            if (adjA[nt].y <= 0) S[nt][1] = -1e30f;
            if (adjB[nt].x <= 0) S[nt][2] = -1e30f;
            if (adjB[nt].y <= 0) S[nt][3] = -1e30f;
            rmax0 = fmaxf(rmax0, fmaxf(S[nt][0], S[nt][1]));
            rmax1 = fmaxf(rmax1, fmaxf(S[nt][2], S[nt][3]));
        }
        rmax0 = fmaxf(rmax0, __shfl_xor_sync(0xffffffffu, rmax0, 1));
        rmax0 = fmaxf(rmax0, __shfl_xor_sync(0xffffffffu, rmax0, 2));
        rmax1 = fmaxf(rmax1, __shfl_xor_sync(0xffffffffu, rmax1, 1));
        rmax1 = fmaxf(rmax1, __shfl_xor_sync(0xffffffffu, rmax1, 2));

        float mn0 = fmaxf(m0, rmax0), mn1 = fmaxf(m1, rmax1);
        float sc0 = __expf(m0 - mn0), sc1 = __expf(m1 - mn1);
        m0 = mn0; m1 = mn1;

        // ---- exp + pack P into fp16 A-fragments ---------------------
        float rs0 = 0.f, rs1 = 0.f;
        unsigned ap[4][4];
#pragma unroll
        for (int kt2 = 0; kt2 < 4; kt2++) {
#pragma unroll
            for (int half = 0; half < 2; half++) {
                int nt = 2 * kt2 + half;
                float p0 = (S[nt][0] > -1e29f) ? __expf(S[nt][0] - mn0) : 0.f;
                float p1 = (S[nt][1] > -1e29f) ? __expf(S[nt][1] - mn0) : 0.f;
                float p2 = (S[nt][2] > -1e29f) ? __expf(S[nt][2] - mn1) : 0.f;
                float p3 = (S[nt][3] > -1e29f) ? __expf(S[nt][3] - mn1) : 0.f;
                rs0 += p0 + p1;
                rs1 += p2 + p3;
                ap[kt2][2 * half + 0] = pack_h2(__float2half_rn(p0), __float2half_rn(p1)); // row g
                ap[kt2][2 * half + 1] = pack_h2(__float2half_rn(p2), __float2half_rn(p3)); // row g+8
            }
        }

        rs0 += __shfl_xor_sync(0xffffffffu, rs0, 1);
        rs0 += __shfl_xor_sync(0xffffffffu, rs0, 2);
        rs1 += __shfl_xor_sync(0xffffffffu, rs1, 1);
        rs1 += __shfl_xor_sync(0xffffffffu, rs1, 2);
        l0 = l0 * sc0 + rs0;
        l1 = l1 * sc1 + rs1;

        // ---- rescale O ----------------------------------------------
#pragma unroll
        for (int v = 0; v < 16; v++) {
            O[v][0] *= sc0; O[v][1] *= sc0;
            O[v][2] *= sc1; O[v][3] *= sc1;
        }

        // ---- O += P V (single fp16 term, chains interleaved x4) -----
#pragma unroll
        for (int kt2 = 0; kt2 < 4; kt2++) {
#pragma unroll
            for (int gr = 0; gr < 4; gr++) {          // vn groups of 4
                unsigned v0[4], v1[4];
#pragma unroll
                for (int i = 0; i < 4; i++) {
                    int vn = 4 * gr + i;
                    int bi = (8 * vn + lr) * KSTRW + qi + 8 * kt2;
                    v0[i] = sV32[bi]; v1[i] = sV32[bi + 4];
                }
#pragma unroll
                for (int i = 0; i < 4; i++)
                    mma_f16(O[4*gr+i], ap[kt2][0], ap[kt2][1], ap[kt2][2], ap[kt2][3], v0[i], v1[i]);
            }
        }
        __syncthreads();  // all warps done reading before next refill
        buf ^= 1;
    }

    // ---- store partials (unnormalized) ------------------------------
    float* op = &g_Op[jhalf][0][0];
#pragma unroll
    for (int vn = 0; vn < 16; vn++) {
        int col = 8 * vn + 2 * qi;
        *(float2*)&op[row0 * OUT_F + col] = make_float2(O[vn][0], O[vn][1]);
        *(float2*)&op[row1 * OUT_F + col] = make_float2(O[vn][2], O[vn][3]);
    }
    if (qi == 0) {
        g_pm[jhalf][row0] = m0; g_pl[jhalf][row0] = l0;
        g_pm[jhalf][row1] = m1; g_pl[jhalf][row1] = l1;
    }
}

// ---------------- merge the two j-halves ----------------------------------
// grid 1024 x 256: block = 8 rows, thread = 4 cols
__global__ __launch_bounds__(256)
void merge_kernel(float* __restrict__ out) {
    const int row = blockIdx.x * 8 + (threadIdx.x >> 5);
    const int c   = (threadIdx.x & 31) * 4;

    float ma = g_pm[0][row], mb = g_pm[1][row];
    float la = g_pl[0][row], lb = g_pl[1][row];
    float M  = fmaxf(ma, mb);
    float sa = __expf(ma - M), sb = __expf(mb - M);
    float inv = 1.f / (la * sa + lb * sb);

    float4 a = *(const float4*)&g_Op[0][row][c];
    float4 b = *(const float4*)&g_Op[1][row][c];
    float4 r;
    r.x = (a.x * sa + b.x * sb) * inv;
    r.y = (a.y * sa + b.y * sb) * inv;
    r.z = (a.z * sa + b.z * sb) * inv;
    r.w = (a.w * sa + b.w * sb) * inv;
    *(float4*)&out[row * OUT_F + c] = r;
}

// ---------------- launch --------------------------------------------------
extern "C" void kernel_launch(void* const* d_in, const int* in_sizes, int n_in,
                              void* d_out, int out_size) {
    const float* h   = (const float*)d_in[0];
    const int*   adj = (const int*)d_in[1];
    const float* Ws  = (const float*)d_in[2];
    const float* Wt  = (const float*)d_in[3];
    const float* Wc  = (const float*)d_in[4];
    float* out = (float*)d_out;

    prep_kernel<<<N_NODES / 4, 128>>>(h, Ws, Wt, Wc);

    const int smem_bytes = 2 * BUF_U4 * 16;   // 73728 B
    cudaFuncSetAttribute(flash_kernel,
                         cudaFuncAttributeMaxDynamicSharedMemorySize, smem_bytes);
    flash_kernel<<<256, 128, smem_bytes>>>(adj);

    merge_kernel<<<N_NODES / 8, 256>>>(out);
}

// round 9
// speedup vs baseline: 2.4808x; 1.1354x over previous
#include <cuda_runtime.h>
#include <cuda_bf16.h>
#include <cuda_fp16.h>
#include <cstdint>

#define N_NODES 8192
#define IN_F    128
#define HID     64
#define OUT_F   128
#define BM      64
#define BN      64
#define NITER   64          // per CTA after j-split (4096 / BN)

// K/V row stride in flash smem: 64 elems + 8 pad = 72 x 2B = 36 words = 9 uint4.
#define KSTRW 36
#define KSTR4 9
// uint4 per buffer: Kh 576, Kl 576, V 1152 -> 2304 u4 = 36864 B ; 3 buffers
#define BUF_U4 2304
#define FLASH_SMEM (3 * BUF_U4 * 16)

// gemm_prep smem B row stride: 128 bf16 = 64 words data + 4 pad = 68 words = 17 u4
#define PSTRW 68
#define PSTR4 17
#define PREP_SMEM (2 * 128 * PSTRW * 4)   // Bh + Bl = 69632 B

// ---------------- scratch (static device globals; no allocs allowed) -----
__device__ __align__(16) __nv_bfloat16 g_hh[N_NODES * IN_F];   // h hi
__device__ __align__(16) __nv_bfloat16 g_hl[N_NODES * IN_F];   // h lo
__device__ __align__(16) __nv_bfloat16 g_Wth[256 * IN_F];      // Wcat^T hi [col][k]
__device__ __align__(16) __nv_bfloat16 g_Wtl[256 * IN_F];      // Wcat^T lo
__device__ __align__(16) __nv_bfloat16 g_Qh[N_NODES * HID];
__device__ __align__(16) __nv_bfloat16 g_Ql[N_NODES * HID];
__device__ __align__(16) __nv_bfloat16 g_Kh[N_NODES * HID];
__device__ __align__(16) __nv_bfloat16 g_Kl[N_NODES * HID];
__device__ __align__(16) __half g_Vt[OUT_F * N_NODES];         // V^T fp16 [feat][j]
__device__ __align__(16) float g_Op[2][N_NODES][OUT_F];
__device__ float g_pm[2][N_NODES];
__device__ float g_pl[2][N_NODES];

// ---------------- helpers --------------------------------------------------
__device__ __forceinline__ void cp16(void* s, const void* g) {
    unsigned sa = (unsigned)__cvta_generic_to_shared(s);
    asm volatile("cp.async.cg.shared.global [%0], [%1], 16;\n" :: "r"(sa), "l"(g));
}
__device__ __forceinline__ void cp_commit() { asm volatile("cp.async.commit_group;\n"); }
template <int N> __device__ __forceinline__ void cp_wait() {
    asm volatile("cp.async.wait_group %0;\n" :: "n"(N));
}
__device__ __forceinline__ void mma_bf16(float c[4],
                                         unsigned a0, unsigned a1, unsigned a2, unsigned a3,
                                         unsigned b0, unsigned b1) {
    asm volatile(
        "mma.sync.aligned.m16n8k16.row.col.f32.bf16.bf16.f32 "
        "{%0,%1,%2,%3}, {%4,%5,%6,%7}, {%8,%9}, {%0,%1,%2,%3};\n"
        : "+f"(c[0]), "+f"(c[1]), "+f"(c[2]), "+f"(c[3])
        : "r"(a0), "r"(a1), "r"(a2), "r"(a3), "r"(b0), "r"(b1));
}
__device__ __forceinline__ void mma_f16(float c[4],
                                        unsigned a0, unsigned a1, unsigned a2, unsigned a3,
                                        unsigned b0, unsigned b1) {
    asm volatile(
        "mma.sync.aligned.m16n8k16.row.col.f32.f16.f16.f32 "
        "{%0,%1,%2,%3}, {%4,%5,%6,%7}, {%8,%9}, {%0,%1,%2,%3};\n"
        : "+f"(c[0]), "+f"(c[1]), "+f"(c[2]), "+f"(c[3])
        : "r"(a0), "r"(a1), "r"(a2), "r"(a3), "r"(b0), "r"(b1));
}
__device__ __forceinline__ unsigned pack_bf2(__nv_bfloat16 a, __nv_bfloat16 b) {
    return (unsigned)__bfloat16_as_ushort(a) |
           ((unsigned)__bfloat16_as_ushort(b) << 16);
}
__device__ __forceinline__ unsigned pack_h2(__half a, __half b) {
    return (unsigned)__half_as_ushort(a) |
           ((unsigned)__half_as_ushort(b) << 16);
}
__device__ __forceinline__ void split_bf(float v, __nv_bfloat16& hi, __nv_bfloat16& lo) {
    hi = __float2bfloat16(v);
    lo = __float2bfloat16(v - __bfloat162float(hi));
}

// ---------------- split: h and Wcat^T -> bf16 hi/lo ------------------------
// grid 1056 x 256: blocks 0..1023 handle h (4 floats/thread); 1024..1055 handle W.
__global__ __launch_bounds__(256)
void split_kernel(const float* __restrict__ h,
                  const float* __restrict__ Ws,
                  const float* __restrict__ Wt,
                  const float* __restrict__ Wc) {
    const int bid = blockIdx.x;
    if (bid < 1024) {
        int idx = (bid * 256 + threadIdx.x) * 4;
        float4 v = *(const float4*)(h + idx);
        union { __nv_bfloat16 b[4]; uint2 u; } ph, pl;
        split_bf(v.x, ph.b[0], pl.b[0]);
        split_bf(v.y, ph.b[1], pl.b[1]);
        split_bf(v.z, ph.b[2], pl.b[2]);
        split_bf(v.w, ph.b[3], pl.b[3]);
        *(uint2*)(g_hh + idx) = ph.u;
        *(uint2*)(g_hl + idx) = pl.u;
    } else {
        int t = (bid - 1024) * 256 + threadIdx.x;   // 0..8191
        int c  = t >> 5;                            // concat col 0..255
        int k0 = (t & 31) * 4;
        const float* W; int stride, cc;
        if (c < 64)       { W = Ws; stride = 64;  cc = c; }
        else if (c < 128) { W = Wt; stride = 64;  cc = c - 64; }
        else              { W = Wc; stride = 128; cc = c - 128; }
        union { __nv_bfloat16 b[4]; uint2 u; } ph, pl;
#pragma unroll
        for (int j = 0; j < 4; j++)
            split_bf(W[(k0 + j) * stride + cc], ph.b[j], pl.b[j]);
        *(uint2*)(g_Wth + c * IN_F + k0) = ph.u;
        *(uint2*)(g_Wtl + c * IN_F + k0) = pl.u;
    }
}

// ---------------- gemm_prep: C = h @ Wcat (3-term bf16) --------------------
// grid 256: mtile = bx & 127 (64 rows), ntile = bx >> 7 (128 cols). 128 threads.
__global__ __launch_bounds__(128, 2)
void gemm_prep() {
    extern __shared__ __align__(16) unsigned char psmem[];
    unsigned* sBh = (unsigned*)psmem;                    // [128][68 words]
    unsigned* sBl = sBh + 128 * PSTRW;

    const int tid  = threadIdx.x;
    const int warp = tid >> 5;
    const int lane = tid & 31;
    const int lr   = lane >> 2;
    const int qi   = lane & 3;

    const int mtile = blockIdx.x & 127;
    const int ntile = blockIdx.x >> 7;
    const int row0  = mtile * 64 + warp * 16 + lr;
    const int row1  = row0 + 8;

    // fill B tile: 128 cols x 128 k, hi+lo (16 u4 per row, stride 17)
    {
        const uint4* gWh4 = (const uint4*)g_Wth;
        const uint4* gWl4 = (const uint4*)g_Wtl;
        uint4* sBh4 = (uint4*)sBh;
        uint4* sBl4 = (uint4*)sBl;
#pragma unroll
        for (int i = tid; i < 2048; i += 128) {
            int r = i >> 4, u = i & 15;
            cp16(&sBh4[r * PSTR4 + u], &gWh4[(ntile * 128 + r) * 16 + u]);
            cp16(&sBl4[r * PSTR4 + u], &gWl4[(ntile * 128 + r) * 16 + u]);
        }
        cp_commit();
    }

    // A fragments (h hi/lo), 8 k-tiles of 16
    const unsigned* hh32 = (const unsigned*)g_hh;
    const unsigned* hl32 = (const unsigned*)g_hl;
    unsigned ah[8][4], al[8][4];
#pragma unroll
    for (int kt = 0; kt < 8; kt++) {
        int b0 = row0 * 64 + qi + 8 * kt;
        int b1 = row1 * 64 + qi + 8 * kt;
        ah[kt][0] = hh32[b0];     ah[kt][1] = hh32[b1];
        ah[kt][2] = hh32[b0 + 4]; ah[kt][3] = hh32[b1 + 4];
        al[kt][0] = hl32[b0];     al[kt][1] = hl32[b1];
        al[kt][2] = hl32[b0 + 4]; al[kt][3] = hl32[b1 + 4];
    }

    float C[16][4];
#pragma unroll
    for (int nt = 0; nt < 16; nt++)
        C[nt][0] = C[nt][1] = C[nt][2] = C[nt][3] = 0.f;

    cp_wait<0>();
    __syncthreads();

#pragma unroll
    for (int kt = 0; kt < 8; kt++) {
#pragma unroll
        for (int g2 = 0; g2 < 4; g2++) {
            unsigned b0[4], b1[4], c0[4], c1[4];
#pragma unroll
            for (int i = 0; i < 4; i++) {
                int nt = 4 * g2 + i;
                int bi = (8 * nt + lr) * PSTRW + qi + 8 * kt;
                b0[i] = sBh[bi]; b1[i] = sBh[bi + 4];
                c0[i] = sBl[bi]; c1[i] = sBl[bi + 4];
            }
#pragma unroll
            for (int i = 0; i < 4; i++)
                mma_bf16(C[4*g2+i], ah[kt][0], ah[kt][1], ah[kt][2], ah[kt][3], b0[i], b1[i]);
#pragma unroll
            for (int i = 0; i < 4; i++)
                mma_bf16(C[4*g2+i], al[kt][0], al[kt][1], al[kt][2], al[kt][3], b0[i], b1[i]);
#pragma unroll
            for (int i = 0; i < 4; i++)
                mma_bf16(C[4*g2+i], ah[kt][0], ah[kt][1], ah[kt][2], ah[kt][3], c0[i], c1[i]);
        }
    }

    // epilogue
    if (ntile == 0) {
        // cols 0..63 -> Q, 64..127 -> K ; bf16 hi/lo, row-major [row][64]
#pragma unroll
        for (int nt = 0; nt < 16; nt++) {
            __nv_bfloat16 h0, l0, h1, l1, h2, l2, h3, l3;
            split_bf(C[nt][0], h0, l0); split_bf(C[nt][1], h1, l1);
            split_bf(C[nt][2], h2, l2); split_bf(C[nt][3], h3, l3);
            int col = 8 * nt + 2 * qi;
            __nv_bfloat16* dh = (col < 64) ? g_Qh : g_Kh;
            __nv_bfloat16* dl = (col < 64) ? g_Ql : g_Kl;
            int c = col & 63;
            *(unsigned*)&dh[(size_t)row0 * HID + c] = pack_bf2(h0, h1);
            *(unsigned*)&dl[(size_t)row0 * HID + c] = pack_bf2(l0, l1);
            *(unsigned*)&dh[(size_t)row1 * HID + c] = pack_bf2(h2, h3);
            *(unsigned*)&dl[(size_t)row1 * HID + c] = pack_bf2(l2, l3);
        }
    } else {
        // cols 128..255 -> V feature cols 0..127, stored transposed fp16
#pragma unroll
        for (int nt = 0; nt < 16; nt++) {
            int col = 8 * nt + 2 * qi;   // V feature col
            g_Vt[(size_t)col       * N_NODES + row0] = __float2half_rn(C[nt][0]);
            g_Vt[(size_t)(col + 1) * N_NODES + row0] = __float2half_rn(C[nt][1]);
            g_Vt[(size_t)col       * N_NODES + row1] = __float2half_rn(C[nt][2]);
            g_Vt[(size_t)(col + 1) * N_NODES + row1] = __float2half_rn(C[nt][3]);
        }
    }
}

// ---------------- flash attention ------------------------------------------
// grid = 256 CTAs: m-tile = bx & 127, j-half = bx >> 7. 128 threads.
__global__ __launch_bounds__(128, 2)
void flash_kernel(const int* __restrict__ adj) {
    extern __shared__ __align__(16) unsigned char dynsmem[];
    uint4* base4 = (uint4*)dynsmem;

    const int tid  = threadIdx.x;
    const int warp = tid >> 5;
    const int lane = tid & 31;
    const int lr   = lane >> 2;
    const int qi   = lane & 3;

    const int mtile = blockIdx.x & 127;
    const int jhalf = blockIdx.x >> 7;
    const int jbase = jhalf * (N_NODES / 2);

    const int mr   = mtile * BM + warp * 16;
    const int row0 = mr + lr;
    const int row1 = row0 + 8;

    // Q fragments (hi/lo)
    const unsigned* qh32 = (const unsigned*)g_Qh;
    const unsigned* ql32 = (const unsigned*)g_Ql;
    unsigned qh[4][4], ql[4][4];
#pragma unroll
    for (int kt = 0; kt < 4; kt++) {
        int b0 = row0 * 32 + qi + 8 * kt;
        int b1 = row1 * 32 + qi + 8 * kt;
        qh[kt][0] = qh32[b0];     qh[kt][1] = qh32[b1];
        qh[kt][2] = qh32[b0 + 4]; qh[kt][3] = qh32[b1 + 4];
        ql[kt][0] = ql32[b0];     ql[kt][1] = ql32[b1];
        ql[kt][2] = ql32[b0 + 4]; ql[kt][3] = ql32[b1 + 4];
    }

    float O[16][4];
#pragma unroll
    for (int v = 0; v < 16; v++)
#pragma unroll
        for (int i = 0; i < 4; i++) O[v][i] = 0.f;
    float m0 = -1e30f, m1 = -1e30f, l0 = 0.f, l1 = 0.f;

    const int2*  adj2 = (const int2*)adj;
    const uint4* gKh4 = (const uint4*)g_Kh;
    const uint4* gKl4 = (const uint4*)g_Kl;
    const uint4* gV4  = (const uint4*)g_Vt;

    // prologue: fill buffer 0
    {
        uint4* bKh = base4;
        uint4* bKl = base4 + 576;
        uint4* bV  = base4 + 1152;
#pragma unroll
        for (int i = tid; i < 512; i += 128) {
            int r = i >> 3, cw = i & 7;
            cp16(&bKh[r * KSTR4 + cw], &gKh4[(jbase + r) * 8 + cw]);
            cp16(&bKl[r * KSTR4 + cw], &gKl4[(jbase + r) * 8 + cw]);
        }
#pragma unroll
        for (int i = tid; i < 1024; i += 128) {
            int cl = i >> 3, kw = i & 7;
            cp16(&bV[cl * KSTR4 + kw], &gV4[cl * 1024 + (jbase >> 3) + kw]);
        }
        cp_commit();
    }

    int b_cur = 0;
    for (int it = 0; it < NITER; ++it) {
        const int j0 = jbase + it * BN;

        // adj prefetch (each quad covers one full 32B sector)
        int2 adjA[8], adjB[8];
#pragma unroll
        for (int nt = 0; nt < 8; nt++) {
            adjA[nt] = __ldcs(&adj2[row0 * 4096 + (j0 >> 1) + 4 * nt + qi]);
            adjB[nt] = __ldcs(&adj2[row1 * 4096 + (j0 >> 1) + 4 * nt + qi]);
        }

        cp_wait<0>();
        __syncthreads();   // SINGLE barrier per iter (3-buffer reuse distance = 2 iters)

        // issue fill of buffer (it+1)%3 — overlaps with this iteration's compute
        if (it + 1 < NITER) {
            const int jn = j0 + BN;
            const int b_nxt = (b_cur == 2) ? 0 : b_cur + 1;
            uint4* bKh = base4 + b_nxt * BUF_U4;
            uint4* bKl = bKh + 576;
            uint4* bV  = bKh + 1152;
#pragma unroll
            for (int i = tid; i < 512; i += 128) {
                int r = i >> 3, cw = i & 7;
                cp16(&bKh[r * KSTR4 + cw], &gKh4[(jn + r) * 8 + cw]);
                cp16(&bKl[r * KSTR4 + cw], &gKl4[(jn + r) * 8 + cw]);
            }
#pragma unroll
            for (int i = tid; i < 1024; i += 128) {
                int cl = i >> 3, kw = i & 7;
                cp16(&bV[cl * KSTR4 + kw], &gV4[cl * 1024 + (jn >> 3) + kw]);
            }
            cp_commit();
        }

        const unsigned* sKh32 = (const unsigned*)(base4 + b_cur * BUF_U4);
        const unsigned* sKl32 = sKh32 + 576 * 4;
        const unsigned* sV32  = sKh32 + 1152 * 4;

        // S = Q K^T (3-term bf16 split, chains interleaved x4)
        float S[8][4];
#pragma unroll
        for (int nt = 0; nt < 8; nt++)
            S[nt][0] = S[nt][1] = S[nt][2] = S[nt][3] = 0.f;

#pragma unroll
        for (int kt = 0; kt < 4; kt++) {
#pragma unroll
            for (int gr = 0; gr < 2; gr++) {
                unsigned b0[4], b1[4], c0[4], c1[4];
#pragma unroll
                for (int i = 0; i < 4; i++) {
                    int nt = 4 * gr + i;
                    int bi = (8 * nt + lr) * KSTRW + qi + 8 * kt;
                    b0[i] = sKh32[bi]; b1[i] = sKh32[bi + 4];
                    c0[i] = sKl32[bi]; c1[i] = sKl32[bi + 4];
                }
#pragma unroll
                for (int i = 0; i < 4; i++)
                    mma_bf16(S[4*gr+i], qh[kt][0], qh[kt][1], qh[kt][2], qh[kt][3], b0[i], b1[i]);
#pragma unroll
                for (int i = 0; i < 4; i++)
                    mma_bf16(S[4*gr+i], ql[kt][0], ql[kt][1], ql[kt][2], ql[kt][3], b0[i], b1[i]);
#pragma unroll
                for (int i = 0; i < 4; i++)
                    mma_bf16(S[4*gr+i], qh[kt][0], qh[kt][1], qh[kt][2], qh[kt][3], c0[i], c1[i]);
            }
        }

        // mask + row max
        float rmax0 = -1e30f, rmax1 = -1e30f;
#pragma unroll
        for (int nt = 0; nt < 8; nt++) {
            if (adjA[nt].x <= 0) S[nt][0] = -1e30f;
            if (adjA[nt].y <= 0) S[nt][1] = -1e30f;
            if (adjB[nt].x <= 0) S[nt][2] = -1e30f;
            if (adjB[nt].y <= 0) S[nt][3] = -1e30f;
            rmax0 = fmaxf(rmax0, fmaxf(S[nt][0], S[nt][1]));
            rmax1 = fmaxf(rmax1, fmaxf(S[nt][2], S[nt][3]));
        }
        rmax0 = fmaxf(rmax0, __shfl_xor_sync(0xffffffffu, rmax0, 1));
        rmax0 = fmaxf(rmax0, __shfl_xor_sync(0xffffffffu, rmax0, 2));
        rmax1 = fmaxf(rmax1, __shfl_xor_sync(0xffffffffu, rmax1, 1));
        rmax1 = fmaxf(rmax1, __shfl_xor_sync(0xffffffffu, rmax1, 2));

        float mn0 = fmaxf(m0, rmax0), mn1 = fmaxf(m1, rmax1);
        float sc0 = __expf(m0 - mn0), sc1 = __expf(m1 - mn1);
        m0 = mn0; m1 = mn1;

        // exp + pack P (fp16)
        float rs0 = 0.f, rs1 = 0.f;
        unsigned ap[4][4];
#pragma unroll
        for (int kt2 = 0; kt2 < 4; kt2++) {
#pragma unroll
            for (int half = 0; half < 2; half++) {
                int nt = 2 * kt2 + half;
                float p0 = (S[nt][0] > -1e29f) ? __expf(S[nt][0] - mn0) : 0.f;
                float p1 = (S[nt][1] > -1e29f) ? __expf(S[nt][1] - mn0) : 0.f;
                float p2 = (S[nt][2] > -1e29f) ? __expf(S[nt][2] - mn1) : 0.f;
                float p3 = (S[nt][3] > -1e29f) ? __expf(S[nt][3] - mn1) : 0.f;
                rs0 += p0 + p1;
                rs1 += p2 + p3;
                ap[kt2][2 * half + 0] = pack_h2(__float2half_rn(p0), __float2half_rn(p1));
                ap[kt2][2 * half + 1] = pack_h2(__float2half_rn(p2), __float2half_rn(p3));
            }
        }

        rs0 += __shfl_xor_sync(0xffffffffu, rs0, 1);
        rs0 += __shfl_xor_sync(0xffffffffu, rs0, 2);
        rs1 += __shfl_xor_sync(0xffffffffu, rs1, 1);
        rs1 += __shfl_xor_sync(0xffffffffu, rs1, 2);
        l0 = l0 * sc0 + rs0;
        l1 = l1 * sc1 + rs1;

        // rescale O only when some row max actually moved (warp-uniform skip)
        if (!__all_sync(0xffffffffu, (sc0 == 1.f) & (sc1 == 1.f))) {
#pragma unroll
            for (int v = 0; v < 16; v++) {
                O[v][0] *= sc0; O[v][1] *= sc0;
                O[v][2] *= sc1; O[v][3] *= sc1;
            }
        }

        // O += P V (single fp16 term, chains interleaved x4)
#pragma unroll
        for (int kt2 = 0; kt2 < 4; kt2++) {
#pragma unroll
            for (int gr = 0; gr < 4; gr++) {
                unsigned v0[4], v1[4];
#pragma unroll
                for (int i = 0; i < 4; i++) {
                    int vn = 4 * gr + i;
                    int bi = (8 * vn + lr) * KSTRW + qi + 8 * kt2;
                    v0[i] = sV32[bi]; v1[i] = sV32[bi + 4];
                }
#pragma unroll
                for (int i = 0; i < 4; i++)
                    mma_f16(O[4*gr+i], ap[kt2][0], ap[kt2][1], ap[kt2][2], ap[kt2][3], v0[i], v1[i]);
            }
        }

        b_cur = (b_cur == 2) ? 0 : b_cur + 1;
    }

    // store partials (unnormalized)
    float* op = &g_Op[jhalf][0][0];
#pragma unroll
    for (int vn = 0; vn < 16; vn++) {
        int col = 8 * vn + 2 * qi;
        *(float2*)&op[row0 * OUT_F + col] = make_float2(O[vn][0], O[vn][1]);
        *(float2*)&op[row1 * OUT_F + col] = make_float2(O[vn][2], O[vn][3]);
    }
    if (qi == 0) {
        g_pm[jhalf][row0] = m0; g_pl[jhalf][row0] = l0;
        g_pm[jhalf][row1] = m1; g_pl[jhalf][row1] = l1;
    }
}

// ---------------- merge the two j-halves ----------------------------------
__global__ __launch_bounds__(256)
void merge_kernel(float* __restrict__ out) {
    const int row = blockIdx.x * 8 + (threadIdx.x >> 5);
    const int c   = (threadIdx.x & 31) * 4;

    float ma = g_pm[0][row], mb = g_pm[1][row];
    float la = g_pl[0][row], lb = g_pl[1][row];
    float M  = fmaxf(ma, mb);
    float sa = __expf(ma - M), sb = __expf(mb - M);
    float inv = 1.f / (la * sa + lb * sb);

    float4 a = *(const float4*)&g_Op[0][row][c];
    float4 b = *(const float4*)&g_Op[1][row][c];
    float4 r;
    r.x = (a.x * sa + b.x * sb) * inv;
    r.y = (a.y * sa + b.y * sb) * inv;
    r.z = (a.z * sa + b.z * sb) * inv;
    r.w = (a.w * sa + b.w * sb) * inv;
    *(float4*)&out[row * OUT_F + c] = r;
}

// ---------------- launch --------------------------------------------------
extern "C" void kernel_launch(void* const* d_in, const int* in_sizes, int n_in,
                              void* d_out, int out_size) {
    const float* h   = (const float*)d_in[0];
    const int*   adj = (const int*)d_in[1];
    const float* Ws  = (const float*)d_in[2];
    const float* Wt  = (const float*)d_in[3];
    const float* Wc  = (const float*)d_in[4];
    float* out = (float*)d_out;

    split_kernel<<<1056, 256>>>(h, Ws, Wt, Wc);

    cudaFuncSetAttribute(gemm_prep,
                         cudaFuncAttributeMaxDynamicSharedMemorySize, PREP_SMEM);
    gemm_prep<<<256, 128, PREP_SMEM>>>();

    cudaFuncSetAttribute(flash_kernel,
                         cudaFuncAttributeMaxDynamicSharedMemorySize, FLASH_SMEM);
    flash_kernel<<<256, 128, FLASH_SMEM>>>(adj);

    merge_kernel<<<N_NODES / 8, 256>>>(out);
}

// round 10
// speedup vs baseline: 2.7048x; 1.0903x over previous
#include <cuda_runtime.h>
#include <cuda_bf16.h>
#include <cuda_fp16.h>
#include <cstdint>

#define N_NODES 8192
#define IN_F    128
#define HID     64
#define OUT_F   128
#define BM      64
#define BN      64

// persistent schedule: 16384 units = 128 mtiles x 128 jblocks, 296 CTAs
// start(c) = 55c + min(c,104)  (CTAs 0..103 have 56 units, rest 55)
#define N_CTAS  296
#define UNIT_Q  55
#define UNIT_R  104
#define CF_THRESH 5824   // start(104) = 55*104+104

// K/V row stride in flash smem: 64 elems + 8 pad = 72 x 2B = 36 words = 9 uint4.
#define KSTRW 36
#define KSTR4 9
// uint4 per buffer: Kh 576, Kl 576, V 1152 -> 2304 u4 = 36864 B ; 3 buffers
#define BUF_U4 2304
#define FLASH_SMEM (3 * BUF_U4 * 16)

// gemm_prep smem B row stride: 128 bf16 = 64 words data + 4 pad = 68 words = 17 u4
#define PSTRW 68
#define PSTR4 17
#define PREP_SMEM (2 * 128 * PSTRW * 4)   // Bh + Bl = 69632 B

// ---------------- scratch (static device globals; no allocs allowed) -----
__device__ __align__(16) __nv_bfloat16 g_hh[N_NODES * IN_F];   // h hi
__device__ __align__(16) __nv_bfloat16 g_hl[N_NODES * IN_F];   // h lo
__device__ __align__(16) __nv_bfloat16 g_Wth[256 * IN_F];      // Wcat^T hi [col][k]
__device__ __align__(16) __nv_bfloat16 g_Wtl[256 * IN_F];      // Wcat^T lo
__device__ __align__(16) __nv_bfloat16 g_Qh[N_NODES * HID];
__device__ __align__(16) __nv_bfloat16 g_Ql[N_NODES * HID];
__device__ __align__(16) __nv_bfloat16 g_Kh[N_NODES * HID];
__device__ __align__(16) __nv_bfloat16 g_Kl[N_NODES * HID];
__device__ __align__(16) __half g_Vt[OUT_F * N_NODES];         // V^T fp16 [feat][j]
// up to 4 partial slots per m-tile
__device__ __align__(16) float g_Op[4][N_NODES][OUT_F];
__device__ float g_pm[4][N_NODES];
__device__ float g_pl[4][N_NODES];

// ---------------- helpers --------------------------------------------------
__device__ __forceinline__ void cp16(void* s, const void* g) {
    unsigned sa = (unsigned)__cvta_generic_to_shared(s);
    asm volatile("cp.async.cg.shared.global [%0], [%1], 16;\n" :: "r"(sa), "l"(g));
}
__device__ __forceinline__ void cp_commit() { asm volatile("cp.async.commit_group;\n"); }
template <int N> __device__ __forceinline__ void cp_wait() {
    asm volatile("cp.async.wait_group %0;\n" :: "n"(N));
}
__device__ __forceinline__ void mma_bf16(float c[4],
                                         unsigned a0, unsigned a1, unsigned a2, unsigned a3,
                                         unsigned b0, unsigned b1) {
    asm volatile(
        "mma.sync.aligned.m16n8k16.row.col.f32.bf16.bf16.f32 "
        "{%0,%1,%2,%3}, {%4,%5,%6,%7}, {%8,%9}, {%0,%1,%2,%3};\n"
        : "+f"(c[0]), "+f"(c[1]), "+f"(c[2]), "+f"(c[3])
        : "r"(a0), "r"(a1), "r"(a2), "r"(a3), "r"(b0), "r"(b1));
}
__device__ __forceinline__ void mma_f16(float c[4],
                                        unsigned a0, unsigned a1, unsigned a2, unsigned a3,
                                        unsigned b0, unsigned b1) {
    asm volatile(
        "mma.sync.aligned.m16n8k16.row.col.f32.f16.f16.f32 "
        "{%0,%1,%2,%3}, {%4,%5,%6,%7}, {%8,%9}, {%0,%1,%2,%3};\n"
        : "+f"(c[0]), "+f"(c[1]), "+f"(c[2]), "+f"(c[3])
        : "r"(a0), "r"(a1), "r"(a2), "r"(a3), "r"(b0), "r"(b1));
}
__device__ __forceinline__ unsigned pack_bf2(__nv_bfloat16 a, __nv_bfloat16 b) {
    return (unsigned)__bfloat16_as_ushort(a) |
           ((unsigned)__bfloat16_as_ushort(b) << 16);
}
__device__ __forceinline__ unsigned pack_h2(__half a, __half b) {
    return (unsigned)__half_as_ushort(a) |
           ((unsigned)__half_as_ushort(b) << 16);
}
__device__ __forceinline__ void split_bf(float v, __nv_bfloat16& hi, __nv_bfloat16& lo) {
    hi = __float2bfloat16(v);
    lo = __float2bfloat16(v - __bfloat162float(hi));
}
__device__ __forceinline__ int cfirst_of(int ut) {
    return (ut < CF_THRESH) ? (ut / 56) : ((ut - UNIT_R) / UNIT_Q);
}

// ---------------- split: h and Wcat^T -> bf16 hi/lo ------------------------
__global__ __launch_bounds__(256)
void split_kernel(const float* __restrict__ h,
                  const float* __restrict__ Ws,
                  const float* __restrict__ Wt,
                  const float* __restrict__ Wc) {
    const int bid = blockIdx.x;
    if (bid < 1024) {
        int idx = (bid * 256 + threadIdx.x) * 4;
        float4 v = *(const float4*)(h + idx);
        union { __nv_bfloat16 b[4]; uint2 u; } ph, pl;
        split_bf(v.x, ph.b[0], pl.b[0]);
        split_bf(v.y, ph.b[1], pl.b[1]);
        split_bf(v.z, ph.b[2], pl.b[2]);
        split_bf(v.w, ph.b[3], pl.b[3]);
        *(uint2*)(g_hh + idx) = ph.u;
        *(uint2*)(g_hl + idx) = pl.u;
    } else {
        int t = (bid - 1024) * 256 + threadIdx.x;   // 0..8191
        int c  = t >> 5;                            // concat col 0..255
        int k0 = (t & 31) * 4;
        const float* W; int stride, cc;
        if (c < 64)       { W = Ws; stride = 64;  cc = c; }
        else if (c < 128) { W = Wt; stride = 64;  cc = c - 64; }
        else              { W = Wc; stride = 128; cc = c - 128; }
        union { __nv_bfloat16 b[4]; uint2 u; } ph, pl;
#pragma unroll
        for (int j = 0; j < 4; j++)
            split_bf(W[(k0 + j) * stride + cc], ph.b[j], pl.b[j]);
        *(uint2*)(g_Wth + c * IN_F + k0) = ph.u;
        *(uint2*)(g_Wtl + c * IN_F + k0) = pl.u;
    }
}

// ---------------- gemm_prep: C = h @ Wcat (3-term bf16) --------------------
// grid 256: mtile = bx & 127 (64 rows), ntile = bx >> 7 (128 cols). 128 threads.
__global__ __launch_bounds__(128, 2)
void gemm_prep() {
    extern __shared__ __align__(16) unsigned char psmem[];
    unsigned* sBh = (unsigned*)psmem;                    // [128][68 words]
    unsigned* sBl = sBh + 128 * PSTRW;

    const int tid  = threadIdx.x;
    const int warp = tid >> 5;
    const int lane = tid & 31;
    const int lr   = lane >> 2;
    const int qi   = lane & 3;

    const int mtile = blockIdx.x & 127;
    const int ntile = blockIdx.x >> 7;
    const int row0  = mtile * 64 + warp * 16 + lr;
    const int row1  = row0 + 8;

    {
        const uint4* gWh4 = (const uint4*)g_Wth;
        const uint4* gWl4 = (const uint4*)g_Wtl;
        uint4* sBh4 = (uint4*)sBh;
        uint4* sBl4 = (uint4*)sBl;
#pragma unroll
        for (int i = tid; i < 2048; i += 128) {
            int r = i >> 4, u = i & 15;
            cp16(&sBh4[r * PSTR4 + u], &gWh4[(ntile * 128 + r) * 16 + u]);
            cp16(&sBl4[r * PSTR4 + u], &gWl4[(ntile * 128 + r) * 16 + u]);
        }
        cp_commit();
    }

    const unsigned* hh32 = (const unsigned*)g_hh;
    const unsigned* hl32 = (const unsigned*)g_hl;
    unsigned ah[8][4], al[8][4];
#pragma unroll
    for (int kt = 0; kt < 8; kt++) {
        int b0 = row0 * 64 + qi + 8 * kt;
        int b1 = row1 * 64 + qi + 8 * kt;
        ah[kt][0] = hh32[b0];     ah[kt][1] = hh32[b1];
        ah[kt][2] = hh32[b0 + 4]; ah[kt][3] = hh32[b1 + 4];
        al[kt][0] = hl32[b0];     al[kt][1] = hl32[b1];
        al[kt][2] = hl32[b0 + 4]; al[kt][3] = hl32[b1 + 4];
    }

    float C[16][4];
#pragma unroll
    for (int nt = 0; nt < 16; nt++)
        C[nt][0] = C[nt][1] = C[nt][2] = C[nt][3] = 0.f;

    cp_wait<0>();
    __syncthreads();

#pragma unroll
    for (int kt = 0; kt < 8; kt++) {
#pragma unroll
        for (int g2 = 0; g2 < 4; g2++) {
            unsigned b0[4], b1[4], c0[4], c1[4];
#pragma unroll
            for (int i = 0; i < 4; i++) {
                int nt = 4 * g2 + i;
                int bi = (8 * nt + lr) * PSTRW + qi + 8 * kt;
                b0[i] = sBh[bi]; b1[i] = sBh[bi + 4];
                c0[i] = sBl[bi]; c1[i] = sBl[bi + 4];
            }
#pragma unroll
            for (int i = 0; i < 4; i++)
                mma_bf16(C[4*g2+i], ah[kt][0], ah[kt][1], ah[kt][2], ah[kt][3], b0[i], b1[i]);
#pragma unroll
            for (int i = 0; i < 4; i++)
                mma_bf16(C[4*g2+i], al[kt][0], al[kt][1], al[kt][2], al[kt][3], b0[i], b1[i]);
#pragma unroll
            for (int i = 0; i < 4; i++)
                mma_bf16(C[4*g2+i], ah[kt][0], ah[kt][1], ah[kt][2], ah[kt][3], c0[i], c1[i]);
        }
    }

    if (ntile == 0) {
#pragma unroll
        for (int nt = 0; nt < 16; nt++) {
            __nv_bfloat16 h0, l0, h1, l1, h2, l2, h3, l3;
            split_bf(C[nt][0], h0, l0); split_bf(C[nt][1], h1, l1);
            split_bf(C[nt][2], h2, l2); split_bf(C[nt][3], h3, l3);
            int col = 8 * nt + 2 * qi;
            __nv_bfloat16* dh = (col < 64) ? g_Qh : g_Kh;
            __nv_bfloat16* dl = (col < 64) ? g_Ql : g_Kl;
            int c = col & 63;
            *(unsigned*)&dh[(size_t)row0 * HID + c] = pack_bf2(h0, h1);
            *(unsigned*)&dl[(size_t)row0 * HID + c] = pack_bf2(l0, l1);
            *(unsigned*)&dh[(size_t)row1 * HID + c] = pack_bf2(h2, h3);
            *(unsigned*)&dl[(size_t)row1 * HID + c] = pack_bf2(l2, l3);
        }
    } else {
#pragma unroll
        for (int nt = 0; nt < 16; nt++) {
            int col = 8 * nt + 2 * qi;
            g_Vt[(size_t)col       * N_NODES + row0] = __float2half_rn(C[nt][0]);
            g_Vt[(size_t)(col + 1) * N_NODES + row0] = __float2half_rn(C[nt][1]);
            g_Vt[(size_t)col       * N_NODES + row1] = __float2half_rn(C[nt][2]);
            g_Vt[(size_t)(col + 1) * N_NODES + row1] = __float2half_rn(C[nt][3]);
        }
    }
}

// ---------------- flash attention (persistent, statically balanced) --------
// grid = 296 CTAs; CTA c owns flattened units [start(c), start(c+1)).
__global__ __launch_bounds__(128, 2)
void flash_kernel(const int* __restrict__ adj) {
    extern __shared__ __align__(16) unsigned char dynsmem[];
    uint4* base4 = (uint4*)dynsmem;

    const int tid  = threadIdx.x;
    const int warp = tid >> 5;
    const int lane = tid & 31;
    const int lr   = lane >> 2;
    const int qi   = lane & 3;

    const int c  = blockIdx.x;
    const int u0 = UNIT_Q * c + min(c, UNIT_R);
    const int u1 = u0 + UNIT_Q + (c < UNIT_R ? 1 : 0);

    const int2*  adj2 = (const int2*)adj;
    const uint4* gKh4 = (const uint4*)g_Kh;
    const uint4* gKl4 = (const uint4*)g_Kl;
    const uint4* gV4  = (const uint4*)g_Vt;
    const unsigned* qh32 = (const unsigned*)g_Qh;
    const unsigned* ql32 = (const unsigned*)g_Ql;

    int u = u0;
    while (u < u1) {
        const int t    = u >> 7;           // m-tile
        const int jb0  = u & 127;          // first j-block in this tile
        const int nit  = min(128 - jb0, u1 - u);
        const int slot = c - cfirst_of(t << 7);
        const int jbase = jb0 * BN;

        const int mr   = t * BM + warp * 16;
        const int row0 = mr + lr;
        const int row1 = row0 + 8;

        // Q fragments (hi/lo)
        unsigned qh[4][4], ql[4][4];
#pragma unroll
        for (int kt = 0; kt < 4; kt++) {
            int b0 = row0 * 32 + qi + 8 * kt;
            int b1 = row1 * 32 + qi + 8 * kt;
            qh[kt][0] = qh32[b0];     qh[kt][1] = qh32[b1];
            qh[kt][2] = qh32[b0 + 4]; qh[kt][3] = qh32[b1 + 4];
            ql[kt][0] = ql32[b0];     ql[kt][1] = ql32[b1];
            ql[kt][2] = ql32[b0 + 4]; ql[kt][3] = ql32[b1 + 4];
        }

        float O[16][4];
#pragma unroll
        for (int v = 0; v < 16; v++)
#pragma unroll
            for (int i = 0; i < 4; i++) O[v][i] = 0.f;
        float m0 = -1e30f, m1 = -1e30f, l0 = 0.f, l1 = 0.f;

        // segment prologue: make smem safe to refill, then fill buffer 0
        __syncthreads();
        {
            uint4* bKh = base4;
            uint4* bKl = base4 + 576;
            uint4* bV  = base4 + 1152;
#pragma unroll
            for (int i = tid; i < 512; i += 128) {
                int r = i >> 3, cw = i & 7;
                cp16(&bKh[r * KSTR4 + cw], &gKh4[(jbase + r) * 8 + cw]);
                cp16(&bKl[r * KSTR4 + cw], &gKl4[(jbase + r) * 8 + cw]);
            }
#pragma unroll
            for (int i = tid; i < 1024; i += 128) {
                int cl = i >> 3, kw = i & 7;
                cp16(&bV[cl * KSTR4 + kw], &gV4[cl * 1024 + (jbase >> 3) + kw]);
            }
            cp_commit();
        }

        int b_cur = 0;
        for (int it = 0; it < nit; ++it) {
            const int j0 = jbase + it * BN;

            int2 adjA[8], adjB[8];
#pragma unroll
            for (int nt = 0; nt < 8; nt++) {
                adjA[nt] = __ldcs(&adj2[row0 * 4096 + (j0 >> 1) + 4 * nt + qi]);
                adjB[nt] = __ldcs(&adj2[row1 * 4096 + (j0 >> 1) + 4 * nt + qi]);
            }

            cp_wait<0>();
            __syncthreads();   // single barrier per iter (3-buffer reuse distance 2)

            if (it + 1 < nit) {
                const int jn = j0 + BN;
                const int b_nxt = (b_cur == 2) ? 0 : b_cur + 1;
                uint4* bKh = base4 + b_nxt * BUF_U4;
                uint4* bKl = bKh + 576;
                uint4* bV  = bKh + 1152;
#pragma unroll
                for (int i = tid; i < 512; i += 128) {
                    int r = i >> 3, cw = i & 7;
                    cp16(&bKh[r * KSTR4 + cw], &gKh4[(jn + r) * 8 + cw]);
                    cp16(&bKl[r * KSTR4 + cw], &gKl4[(jn + r) * 8 + cw]);
                }
#pragma unroll
                for (int i = tid; i < 1024; i += 128) {
                    int cl = i >> 3, kw = i & 7;
                    cp16(&bV[cl * KSTR4 + kw], &gV4[cl * 1024 + (jn >> 3) + kw]);
                }
                cp_commit();
            }

            const unsigned* sKh32 = (const unsigned*)(base4 + b_cur * BUF_U4);
            const unsigned* sKl32 = sKh32 + 576 * 4;
            const unsigned* sV32  = sKh32 + 1152 * 4;

            // S = Q K^T (3-term bf16 split, chains interleaved x4)
            float S[8][4];
#pragma unroll
            for (int nt = 0; nt < 8; nt++)
                S[nt][0] = S[nt][1] = S[nt][2] = S[nt][3] = 0.f;

#pragma unroll
            for (int kt = 0; kt < 4; kt++) {
#pragma unroll
                for (int gr = 0; gr < 2; gr++) {
                    unsigned b0[4], b1[4], c0[4], c1[4];
#pragma unroll
                    for (int i = 0; i < 4; i++) {
                        int nt = 4 * gr + i;
                        int bi = (8 * nt + lr) * KSTRW + qi + 8 * kt;
                        b0[i] = sKh32[bi]; b1[i] = sKh32[bi + 4];
                        c0[i] = sKl32[bi]; c1[i] = sKl32[bi + 4];
                    }
#pragma unroll
                    for (int i = 0; i < 4; i++)
                        mma_bf16(S[4*gr+i], qh[kt][0], qh[kt][1], qh[kt][2], qh[kt][3], b0[i], b1[i]);
#pragma unroll
                    for (int i = 0; i < 4; i++)
                        mma_bf16(S[4*gr+i], ql[kt][0], ql[kt][1], ql[kt][2], ql[kt][3], b0[i], b1[i]);
#pragma unroll
                    for (int i = 0; i < 4; i++)
                        mma_bf16(S[4*gr+i], qh[kt][0], qh[kt][1], qh[kt][2], qh[kt][3], c0[i], c1[i]);
                }
            }

            // mask + row max
            float rmax0 = -1e30f, rmax1 = -1e30f;
#pragma unroll
            for (int nt = 0; nt < 8; nt++) {
                if (adjA[nt].x <= 0) S[nt][0] = -1e30f;
                if (adjA[nt].y <= 0) S[nt][1] = -1e30f;
                if (adjB[nt].x <= 0) S[nt][2] = -1e30f;
                if (adjB[nt].y <= 0) S[nt][3] = -1e30f;
                rmax0 = fmaxf(rmax0, fmaxf(S[nt][0], S[nt][1]));
                rmax1 = fmaxf(rmax1, fmaxf(S[nt][2], S[nt][3]));
            }
            rmax0 = fmaxf(rmax0, __shfl_xor_sync(0xffffffffu, rmax0, 1));
            rmax0 = fmaxf(rmax0, __shfl_xor_sync(0xffffffffu, rmax0, 2));
            rmax1 = fmaxf(rmax1, __shfl_xor_sync(0xffffffffu, rmax1, 1));
            rmax1 = fmaxf(rmax1, __shfl_xor_sync(0xffffffffu, rmax1, 2));

            float mn0 = fmaxf(m0, rmax0), mn1 = fmaxf(m1, rmax1);
            float sc0 = __expf(m0 - mn0), sc1 = __expf(m1 - mn1);
            m0 = mn0; m1 = mn1;

            // exp + pack P (fp16)
            float rs0 = 0.f, rs1 = 0.f;
            unsigned ap[4][4];
#pragma unroll
            for (int kt2 = 0; kt2 < 4; kt2++) {
#pragma unroll
                for (int half = 0; half < 2; half++) {
                    int nt = 2 * kt2 + half;
                    float p0 = (S[nt][0] > -1e29f) ? __expf(S[nt][0] - mn0) : 0.f;
                    float p1 = (S[nt][1] > -1e29f) ? __expf(S[nt][1] - mn0) : 0.f;
                    float p2 = (S[nt][2] > -1e29f) ? __expf(S[nt][2] - mn1) : 0.f;
                    float p3 = (S[nt][3] > -1e29f) ? __expf(S[nt][3] - mn1) : 0.f;
                    rs0 += p0 + p1;
                    rs1 += p2 + p3;
                    ap[kt2][2 * half + 0] = pack_h2(__float2half_rn(p0), __float2half_rn(p1));
                    ap[kt2][2 * half + 1] = pack_h2(__float2half_rn(p2), __float2half_rn(p3));
                }
            }

            rs0 += __shfl_xor_sync(0xffffffffu, rs0, 1);
            rs0 += __shfl_xor_sync(0xffffffffu, rs0, 2);
            rs1 += __shfl_xor_sync(0xffffffffu, rs1, 1);
            rs1 += __shfl_xor_sync(0xffffffffu, rs1, 2);
            l0 = l0 * sc0 + rs0;
            l1 = l1 * sc1 + rs1;

            if (!__all_sync(0xffffffffu, (sc0 == 1.f) & (sc1 == 1.f))) {
#pragma unroll
                for (int v = 0; v < 16; v++) {
                    O[v][0] *= sc0; O[v][1] *= sc0;
                    O[v][2] *= sc1; O[v][3] *= sc1;
                }
            }

            // O += P V (single fp16 term, chains interleaved x4)
#pragma unroll
            for (int kt2 = 0; kt2 < 4; kt2++) {
#pragma unroll
                for (int gr = 0; gr < 4; gr++) {
                    unsigned v0[4], v1[4];
#pragma unroll
                    for (int i = 0; i < 4; i++) {
                        int vn = 4 * gr + i;
                        int bi = (8 * vn + lr) * KSTRW + qi + 8 * kt2;
                        v0[i] = sV32[bi]; v1[i] = sV32[bi + 4];
                    }
#pragma unroll
                    for (int i = 0; i < 4; i++)
                        mma_f16(O[4*gr+i], ap[kt2][0], ap[kt2][1], ap[kt2][2], ap[kt2][3], v0[i], v1[i]);
                }
            }

            b_cur = (b_cur == 2) ? 0 : b_cur + 1;
        }

        // write this segment's partials (unnormalized)
        float* op = &g_Op[slot][0][0];
#pragma unroll
        for (int vn = 0; vn < 16; vn++) {
            int col = 8 * vn + 2 * qi;
            *(float2*)&op[row0 * OUT_F + col] = make_float2(O[vn][0], O[vn][1]);
            *(float2*)&op[row1 * OUT_F + col] = make_float2(O[vn][2], O[vn][3]);
        }
        if (qi == 0) {
            g_pm[slot][row0] = m0; g_pl[slot][row0] = l0;
            g_pm[slot][row1] = m1; g_pl[slot][row1] = l1;
        }

        u += nit;
    }
}

// ---------------- merge variable partial slots -----------------------------
// grid 1024 x 256: block = 8 rows, thread = 4 cols
__global__ __launch_bounds__(256)
void merge_kernel(float* __restrict__ out) {
    const int row = blockIdx.x * 8 + (threadIdx.x >> 5);
    const int cc  = (threadIdx.x & 31) * 4;

    const int t  = row >> 6;
    const int ut = t << 7;
    const int cf = cfirst_of(ut);
    const int cl = cfirst_of(ut + 127);
    const int ns = cl - cf + 1;      // 2..4 partials

    float M = g_pm[0][row];
    float L = g_pl[0][row];
    float4 acc = *(const float4*)&g_Op[0][row][cc];

    for (int s = 1; s < ns; s++) {
        float m = g_pm[s][row], l = g_pl[s][row];
        float Mn = fmaxf(M, m);
        float sa = __expf(M - Mn), sb = __expf(m - Mn);
        float4 b = *(const float4*)&g_Op[s][row][cc];
        acc.x = acc.x * sa + b.x * sb;
        acc.y = acc.y * sa + b.y * sb;
        acc.z = acc.z * sa + b.z * sb;
        acc.w = acc.w * sa + b.w * sb;
        L = L * sa + l * sb;
        M = Mn;
    }

    float inv = 1.f / L;
    float4 r = make_float4(acc.x * inv, acc.y * inv, acc.z * inv, acc.w * inv);
    *(float4*)&out[row * OUT_F + cc] = r;
}

// ---------------- launch --------------------------------------------------
extern "C" void kernel_launch(void* const* d_in, const int* in_sizes, int n_in,
                              void* d_out, int out_size) {
    const float* h   = (const float*)d_in[0];
    const int*   adj = (const int*)d_in[1];
    const float* Ws  = (const float*)d_in[2];
    const float* Wt  = (const float*)d_in[3];
    const float* Wc  = (const float*)d_in[4];
    float* out = (float*)d_out;

    split_kernel<<<1056, 256>>>(h, Ws, Wt, Wc);

    cudaFuncSetAttribute(gemm_prep,
                         cudaFuncAttributeMaxDynamicSharedMemorySize, PREP_SMEM);
    gemm_prep<<<256, 128, PREP_SMEM>>>();

    cudaFuncSetAttribute(flash_kernel,
                         cudaFuncAttributeMaxDynamicSharedMemorySize, FLASH_SMEM);
    flash_kernel<<<N_CTAS, 128, FLASH_SMEM>>>(adj);

    merge_kernel<<<N_NODES / 8, 256>>>(out);
}